// round 13
// baseline (speedup 1.0000x reference)
#include <cuda_runtime.h>
#include <cuda_fp16.h>
#include <cstdint>

#define NMAX   100000
#define EMAX   1600000
#define CDIM   50
#define HLDH   32            // packed H row stride (uint32 = fp16x2), 128 B rows
#define HIDD   256
#define INDIM  500
#define KHOP   10

// ---------------- static scratch (no allocations allowed) ----------------
static __device__ __align__(16) uint32_t g_Hh[(size_t)(KHOP + 1) * NMAX * HLDH];  // fp16x2 planes
static __device__ float    g_norm[NMAX];    // deg^-1/2
static __device__ float    g_nrm2[NMAX];    // deg^-1
static __device__ float    g_sdeg[NMAX];    // deg^+1/2
static __device__ int      g_deg   [NMAX];
static __device__ int      g_rowptr[NMAX + 1];
static __device__ int      g_cursor[NMAX];
static __device__ int      g_bsum  [1024];
static __device__ int      g_col   [EMAX];
static __device__ __align__(16) uint32_t g_w1h[(INDIM / 2) * HIDD];  // W1 k-pair hi plane
static __device__ __align__(16) uint32_t g_w2h[(HIDD / 2) * 64];     // W2 padded ldp=64
static __device__ __align__(16) uint32_t g_w2l[(HIDD / 2) * 64];

// ================= fp16 helpers =================
__device__ __forceinline__ void split2(float x, float y, uint32_t& h2u, uint32_t& l2u) {
    __half2 h = __floats2half2_rn(x, y);
    float2 hf = __half22float2(h);
    __half2 l = __floats2half2_rn(x - hf.x, y - hf.y);
    h2u = *reinterpret_cast<uint32_t*>(&h);
    l2u = *reinterpret_cast<uint32_t*>(&l);
}

__device__ __forceinline__ uint32_t pack_h2(float x, float y) {
    __half2 h = __floats2half2_rn(x, y);
    return *reinterpret_cast<uint32_t*>(&h);
}

__device__ __forceinline__ float2 unpack_h2(uint32_t u) {
    __half2 h = *reinterpret_cast<__half2*>(&u);
    return __half22float2(h);
}

__device__ __forceinline__ void mma_f16(float* c, const uint32_t* a, const uint32_t* b) {
    asm volatile(
        "mma.sync.aligned.m16n8k16.row.col.f32.f16.f16.f32 "
        "{%0,%1,%2,%3}, {%4,%5,%6,%7}, {%8,%9}, {%0,%1,%2,%3};"
        : "+f"(c[0]), "+f"(c[1]), "+f"(c[2]), "+f"(c[3])
        : "r"(a[0]), "r"(a[1]), "r"(a[2]), "r"(a[3]), "r"(b[0]), "r"(b[1]));
}

__device__ __forceinline__ void cp_async16(uint32_t dst, const void* src, int sz) {
    asm volatile("cp.async.ca.shared.global [%0], [%1], 16, %2;"
                 :: "r"(dst), "l"(src), "r"(sz));
}
#define CP_COMMIT() asm volatile("cp.async.commit_group;")
#define CP_WAIT1()  asm volatile("cp.async.wait_group 1;")
#define CP_WAIT0()  asm volatile("cp.async.wait_group 0;")

// W [K][N] fp32 -> packed k-pair fp16 hi plane [K/2][ldp]
__global__ void decomp_hi(const float* __restrict__ W,
                          uint32_t* __restrict__ Wh2, int K, int N, int ldp) {
    int i = blockIdx.x * blockDim.x + threadIdx.x;
    if (i >= (K / 2) * ldp) return;
    int k2 = i / ldp, c = i % ldp;
    float x = (c < N) ? W[(size_t)(2 * k2) * N + c] : 0.f;
    float y = (c < N) ? W[(size_t)(2 * k2 + 1) * N + c] : 0.f;
    Wh2[i] = pack_h2(x, y);
}

// W [K][N] fp32 -> packed hi+lo planes (W2)
__global__ void decomp_pair(const float* __restrict__ W,
                            uint32_t* __restrict__ Wh2, uint32_t* __restrict__ Wl2,
                            int K, int N, int ldp) {
    int i = blockIdx.x * blockDim.x + threadIdx.x;
    if (i >= (K / 2) * ldp) return;
    int k2 = i / ldp, c = i % ldp;
    float x = (c < N) ? W[(size_t)(2 * k2) * N + c] : 0.f;
    float y = (c < N) ? W[(size_t)(2 * k2 + 1) * N + c] : 0.f;
    uint32_t h, l; split2(x, y, h, l);
    Wh2[i] = h; Wl2[i] = l;
}

// ================= fused MLP: t0(fp16) = nrm * (relu(feats@W1+b1) @ W2 + b2) =================
#define TBM1 64
#define TBK  32
#define ASU  20
#define BSTF 264
#define X1ST 132
#define W2ST 72

__global__ __launch_bounds__(256, 2)
void mlp_fused(const float* __restrict__ A,
               const uint32_t* __restrict__ Bh2g,
               const float* __restrict__ bias1,
               const uint32_t* __restrict__ W2hg, const uint32_t* __restrict__ W2lg,
               const float* __restrict__ bias2,
               const float* __restrict__ nrm,
               uint32_t* __restrict__ C, int M, int K) {
    extern __shared__ uint8_t dyn[];
    uint32_t* Ah = (uint32_t*)dyn;                 // [2][64][ASU]
    uint32_t* Bh = Ah + 2 * TBM1 * ASU;            // [2][16][BSTF]
    uint32_t* X1h = (uint32_t*)dyn;                // [64][X1ST]
    uint32_t* X1l = X1h + TBM1 * X1ST;
    uint32_t* W2h = X1l + TBM1 * X1ST;             // [2][16][W2ST]
    uint32_t* W2l = W2h + 2 * 16 * W2ST;

    const uint32_t sBh  = (uint32_t)__cvta_generic_to_shared(Bh);
    const uint32_t sW2h = (uint32_t)__cvta_generic_to_shared(W2h);
    const uint32_t sW2l = (uint32_t)__cvta_generic_to_shared(W2l);

    const int tid  = threadIdx.x;
    const int lane = tid & 31;
    const int wid  = tid >> 5;
    const int g    = lane >> 2;
    const int tg   = lane & 3;
    const int row0 = blockIdx.x * TBM1;
    const int K2   = K / 2;

    const int wm = (wid & 1) * 32;
    const int wn = (wid >> 1) * 64;

    float acc[2][8][4];
#pragma unroll
    for (int i = 0; i < 2; i++)
#pragma unroll
        for (int j = 0; j < 8; j++)
#pragma unroll
            for (int q = 0; q < 4; q++) acc[i][j][q] = 0.f;

    float4 areg[2];
    auto ldgA = [&](int kt) {
#pragma unroll
        for (int q = 0; q < 2; q++) {
            int chunk = tid + q * 256;
            int r = chunk >> 3, c4 = (chunk & 7) * 4;
            int gr = row0 + r, gk = kt + c4;
            float4 v = make_float4(0.f, 0.f, 0.f, 0.f);
            if (gr < M) {
                if (gk + 3 < K) {
                    v = *reinterpret_cast<const float4*>(A + (size_t)gr * K + gk);
                } else if (gk < K) {
                    const float* p = A + (size_t)gr * K;
                    v.x = p[gk];
                    v.y = (gk + 1 < K) ? p[gk + 1] : 0.f;
                    v.z = (gk + 2 < K) ? p[gk + 2] : 0.f;
                    v.w = (gk + 3 < K) ? p[gk + 3] : 0.f;
                }
            }
            areg[q] = v;
        }
    };
    auto stsA = [&](int buf) {
#pragma unroll
        for (int q = 0; q < 2; q++) {
            int chunk = tid + q * 256;
            int r = chunk >> 3, c4 = (chunk & 7) * 4;
            uint32_t h01 = pack_h2(areg[q].x, areg[q].y);
            uint32_t h23 = pack_h2(areg[q].z, areg[q].w);
            int base = (buf * TBM1 + r) * ASU + (c4 >> 1);
            *reinterpret_cast<uint2*>(&Ah[base]) = make_uint2(h01, h23);
        }
    };
    auto cpB = [&](int buf, int kt) {
        int k2t = kt >> 1;
#pragma unroll
        for (int q = 0; q < 4; q++) {
            int chunk = tid + q * 256;
            int r = chunk >> 6, c4 = (chunk & 63) * 4;
            int gk2 = k2t + r;
            int sz = (gk2 < K2) ? 16 : 0;
            const uint32_t* src = Bh2g + (size_t)(gk2 < K2 ? gk2 : 0) * HIDD + c4;
            uint32_t dst = sBh + (uint32_t)(((buf * 16 + r) * BSTF + c4) * 4);
            cp_async16(dst, src, sz);
        }
    };

    const int ktiles = (K + TBK - 1) / TBK;
    ldgA(0); stsA(0);
    cpB(0, 0); CP_COMMIT();

    int buf = 0;
    for (int t = 0; t < ktiles; t++) {
        if (t + 1 < ktiles) {
            ldgA((t + 1) * TBK);
            cpB(buf ^ 1, (t + 1) * TBK);
            CP_COMMIT();
            CP_WAIT1();
        } else {
            CP_WAIT0();
        }
        __syncthreads();

        const uint32_t* ab_h = Ah + buf * TBM1 * ASU;
        const uint32_t* bb_h = Bh + buf * 16 * BSTF;
#pragma unroll
        for (int ks = 0; ks < 2; ks++) {
            const int k2 = ks * 8;
            uint32_t ah[2][4];
#pragma unroll
            for (int mi = 0; mi < 2; mi++) {
                int m = wm + mi * 16;
                ah[mi][0] = ab_h[(m + g    ) * ASU + k2 + tg    ];
                ah[mi][1] = ab_h[(m + g + 8) * ASU + k2 + tg    ];
                ah[mi][2] = ab_h[(m + g    ) * ASU + k2 + 4 + tg];
                ah[mi][3] = ab_h[(m + g + 8) * ASU + k2 + 4 + tg];
            }
#pragma unroll
            for (int ni = 0; ni < 8; ni++) {
                int n = wn + ni * 8;
                uint32_t bh[2];
                bh[0] = bb_h[(k2 + tg    ) * BSTF + n + g];
                bh[1] = bb_h[(k2 + 4 + tg) * BSTF + n + g];
#pragma unroll
                for (int mi = 0; mi < 2; mi++)
                    mma_f16(acc[mi][ni], ah[mi], bh);
            }
        }
        if (t + 1 < ktiles) stsA(buf ^ 1);
        __syncthreads();
        buf ^= 1;
    }

    // ---------------- transition ----------------
    auto loadW2 = [&](int b, int k2t) {
#pragma unroll
        for (int q = 0; q < 2; q++) {
            int chunk = tid + q * 256;
            int plane = chunk >> 8;
            int cc = chunk & 255;
            int r = cc >> 4, c4 = (cc & 15) * 4;
            const uint32_t* src = (plane ? W2lg : W2hg) + (size_t)(k2t + r) * 64 + c4;
            uint32_t dst = (plane ? sW2l : sW2h) + (uint32_t)(((b * 16 + r) * W2ST + c4) * 4);
            cp_async16(dst, src, 16);
        }
    };

    loadW2(0, 0);
    CP_COMMIT();
#pragma unroll
    for (int mi = 0; mi < 2; mi++) {
#pragma unroll
        for (int ni = 0; ni < 8; ni++) {
            int c = wn + ni * 8 + 2 * tg;
            float bv0 = bias1[c], bv1 = bias1[c + 1];
            int rA = wm + mi * 16 + g;
            int rB = rA + 8;
            float v0 = fmaxf(acc[mi][ni][0] + bv0, 0.f);
            float v1 = fmaxf(acc[mi][ni][1] + bv1, 0.f);
            float v2 = fmaxf(acc[mi][ni][2] + bv0, 0.f);
            float v3 = fmaxf(acc[mi][ni][3] + bv1, 0.f);
            uint32_t h, l;
            split2(v0, v1, h, l);
            X1h[rA * X1ST + (c >> 1)] = h;
            X1l[rA * X1ST + (c >> 1)] = l;
            split2(v2, v3, h, l);
            X1h[rB * X1ST + (c >> 1)] = h;
            X1l[rB * X1ST + (c >> 1)] = l;
        }
    }

    // ---------------- phase 2 ----------------
    const int wm2 = (wid & 1) * 32;
    const int wn2 = (wid >> 1) * 16;

    float acc2[2][2][4];
#pragma unroll
    for (int i = 0; i < 2; i++)
#pragma unroll
        for (int j = 0; j < 2; j++)
#pragma unroll
            for (int q = 0; q < 4; q++) acc2[i][j][q] = 0.f;

    int buf2 = 0;
    for (int t = 0; t < 8; t++) {
        if (t + 1 < 8) {
            loadW2(buf2 ^ 1, (t + 1) * 16);
            CP_COMMIT();
            CP_WAIT1();
        } else {
            CP_WAIT0();
        }
        __syncthreads();

        const uint32_t* wb_h = W2h + buf2 * 16 * W2ST;
        const uint32_t* wb_l = W2l + buf2 * 16 * W2ST;
        const int k2base = t * 16;
#pragma unroll
        for (int ks = 0; ks < 2; ks++) {
            const int k2 = ks * 8;
            const int kc = k2base + k2;
            uint32_t ah[2][4], al[2][4], bh[2][2], bl[2][2];
#pragma unroll
            for (int mi = 0; mi < 2; mi++) {
                int m = wm2 + mi * 16;
                ah[mi][0] = X1h[(m + g    ) * X1ST + kc + tg    ];
                ah[mi][1] = X1h[(m + g + 8) * X1ST + kc + tg    ];
                ah[mi][2] = X1h[(m + g    ) * X1ST + kc + 4 + tg];
                ah[mi][3] = X1h[(m + g + 8) * X1ST + kc + 4 + tg];
                al[mi][0] = X1l[(m + g    ) * X1ST + kc + tg    ];
                al[mi][1] = X1l[(m + g + 8) * X1ST + kc + tg    ];
                al[mi][2] = X1l[(m + g    ) * X1ST + kc + 4 + tg];
                al[mi][3] = X1l[(m + g + 8) * X1ST + kc + 4 + tg];
            }
#pragma unroll
            for (int ni = 0; ni < 2; ni++) {
                int n = wn2 + ni * 8;
                bh[ni][0] = wb_h[(k2 + tg    ) * W2ST + n + g];
                bh[ni][1] = wb_h[(k2 + 4 + tg) * W2ST + n + g];
                bl[ni][0] = wb_l[(k2 + tg    ) * W2ST + n + g];
                bl[ni][1] = wb_l[(k2 + 4 + tg) * W2ST + n + g];
            }
#pragma unroll
            for (int mi = 0; mi < 2; mi++)
#pragma unroll
                for (int ni = 0; ni < 2; ni++) {
                    mma_f16(acc2[mi][ni], ah[mi], bh[ni]);
                    mma_f16(acc2[mi][ni], al[mi], bh[ni]);
                    mma_f16(acc2[mi][ni], ah[mi], bl[ni]);
                }
        }
        __syncthreads();
        buf2 ^= 1;
    }

    // epilogue 2: bias2, scale by nrm, write packed fp16 t0 row (stride HLDH)
#pragma unroll
    for (int mi = 0; mi < 2; mi++) {
#pragma unroll
        for (int ni = 0; ni < 2; ni++) {
            int c = wn2 + ni * 8 + 2 * tg;
            if (c >= CDIM) continue;
            float bv0 = bias2[c];
            float bv1 = (c + 1 < CDIM) ? bias2[c + 1] : 0.f;
            int r0 = row0 + wm2 + mi * 16 + g;
            int r1 = r0 + 8;
            if (r0 < M) {
                float nd = nrm[r0];
                float v0 = (acc2[mi][ni][0] + bv0) * nd;
                float v1 = (acc2[mi][ni][1] + bv1) * nd;
                C[(size_t)r0 * HLDH + (c >> 1)] = pack_h2(v0, v1);
            }
            if (r1 < M) {
                float nd = nrm[r1];
                float v2 = (acc2[mi][ni][2] + bv0) * nd;
                float v3 = (acc2[mi][ni][3] + bv1) * nd;
                C[(size_t)r1 * HLDH + (c >> 1)] = pack_h2(v2, v3);
            }
        }
    }
}

// ---------------- CSR build helpers ----------------
__global__ void hist_kernel(const int* __restrict__ dst, int* __restrict__ deg, int E) {
    int i = blockIdx.x * blockDim.x + threadIdx.x;
    if (i < E) atomicAdd(&deg[dst[i]], 1);
}

__global__ void norm_kernel(const int* __restrict__ deg, float* __restrict__ nrm,
                            float* __restrict__ nrm2, float* __restrict__ sdeg, int n) {
    int i = blockIdx.x * blockDim.x + threadIdx.x;
    if (i < n) {
        float d = (float)deg[i];
        nrm[i]  = rsqrtf(d);
        nrm2[i] = 1.0f / d;
        sdeg[i] = sqrtf(d);
    }
}

__global__ void scan_block(const int* __restrict__ deg, int* __restrict__ rowptr,
                           int* __restrict__ bsum, int n) {
    __shared__ int sh[512];
    int tid = threadIdx.x;
    int gid = blockIdx.x * 512 + tid;
    int v = (gid < n) ? deg[gid] : 0;
    sh[tid] = v;
    __syncthreads();
    for (int off = 1; off < 512; off <<= 1) {
        int t = (tid >= off) ? sh[tid - off] : 0;
        __syncthreads();
        sh[tid] += t;
        __syncthreads();
    }
    if (gid < n) rowptr[gid] = sh[tid] - v;
    if (tid == 511) bsum[blockIdx.x] = sh[511];
}

__global__ void scan_sums(int* __restrict__ bsum, int nb) {
    __shared__ int sh[1024];
    int tid = threadIdx.x;
    int v = (tid < nb) ? bsum[tid] : 0;
    sh[tid] = v;
    __syncthreads();
    for (int off = 1; off < 1024; off <<= 1) {
        int t = (tid >= off) ? sh[tid - off] : 0;
        __syncthreads();
        sh[tid] += t;
        __syncthreads();
    }
    if (tid < nb) bsum[tid] = sh[tid] - v;
}

__global__ void scan_finish(int* __restrict__ rowptr, const int* __restrict__ bsum,
                            int* __restrict__ cursor, int n, int E) {
    int gid = blockIdx.x * blockDim.x + threadIdx.x;
    if (gid < n) {
        int r = rowptr[gid] + bsum[gid / 512];
        rowptr[gid] = r;
        cursor[gid] = r;
    }
    if (gid == 0) rowptr[n] = E;
}

__global__ void fill_kernel(const int* __restrict__ src, const int* __restrict__ dst,
                            int* __restrict__ cursor, int* __restrict__ col, int E) {
    int e = blockIdx.x * blockDim.x + threadIdx.x;
    if (e >= E) return;
    int pos = atomicAdd(&cursor[dst[e]], 1);
    col[pos] = src[e];
}

// ---------------- pull-gather hop on packed fp16 planes ----------------
// t_out[d] = fp16( nrm2[d] * sum_{s in N(d)} t_in[s] );  fp32 accumulation
__global__ void spmm_pull(const int* __restrict__ rowptr, const int* __restrict__ col,
                          const float* __restrict__ nrm2,
                          const uint32_t* __restrict__ hin, uint32_t* __restrict__ hout,
                          int N) {
    int t = blockIdx.x * blockDim.x + threadIdx.x;
    int n = t >> 5;
    int lane = t & 31;
    if (n >= N) return;

    int beg = rowptr[n];
    int end = rowptr[n + 1];
    const bool act = (lane < CDIM / 2);

    float ax = 0.f, ay = 0.f;
    int j = beg;
    for (; j + 3 < end; j += 4) {
        int s0 = col[j], s1 = col[j + 1], s2 = col[j + 2], s3 = col[j + 3];
        if (act) {
            float2 v0 = unpack_h2(hin[(size_t)s0 * HLDH + lane]);
            float2 v1 = unpack_h2(hin[(size_t)s1 * HLDH + lane]);
            float2 v2 = unpack_h2(hin[(size_t)s2 * HLDH + lane]);
            float2 v3 = unpack_h2(hin[(size_t)s3 * HLDH + lane]);
            ax += (v0.x + v1.x) + (v2.x + v3.x);
            ay += (v0.y + v1.y) + (v2.y + v3.y);
        }
    }
    for (; j < end; j++) {
        int s0 = col[j];
        if (act) {
            float2 v0 = unpack_h2(hin[(size_t)s0 * HLDH + lane]);
            ax += v0.x;
            ay += v0.y;
        }
    }
    if (act) {
        float w = nrm2[n];
        hout[(size_t)n * HLDH + lane] = pack_h2(w * ax, w * ay);
    }
}

// ---------------- final sigmoid-gated combine (unscale by sqrt(deg)) ----------------
__global__ void final_kernel(const uint32_t* __restrict__ H, const float* __restrict__ s,
                             const float* __restrict__ sdeg,
                             float* __restrict__ out, int N) {
    int t = blockIdx.x * blockDim.x + threadIdx.x;
    int n = t >> 5;
    int lane = t & 31;
    if (n >= N) return;

    const bool act = (lane < CDIM / 2);
    const int  c2  = lane * 2;
    float sx = act ? s[c2] : 0.f;
    float sy = act ? s[c2 + 1] : 0.f;
    float inv = sdeg[n];

    float ax = 0.f, ay = 0.f;
    size_t plane = (size_t)N * HLDH;
    const uint32_t* base = H + (size_t)n * HLDH;

#pragma unroll
    for (int k = 0; k <= KHOP; k++) {
        float2 tv = act ? unpack_h2(base[(size_t)k * plane + lane]) : make_float2(0.f, 0.f);
        float hx = tv.x * inv, hy = tv.y * inv;
        float dot = hx * sx + hy * sy;
#pragma unroll
        for (int off = 16; off; off >>= 1)
            dot += __shfl_xor_sync(0xffffffffu, dot, off);
        float S = 1.f / (1.f + __expf(-dot));
        ax += S * hx;
        ay += S * hy;
    }
    if (act)
        *reinterpret_cast<float2*>(out + (size_t)n * CDIM + c2) = make_float2(ax, ay);
}

// ---------------- launch ----------------
extern "C" void kernel_launch(void* const* d_in, const int* in_sizes, int n_in,
                              void* d_out, int out_size) {
    const float* feats = (const float*)d_in[0];
    const float* W1    = (const float*)d_in[1];
    const float* b1    = (const float*)d_in[2];
    const float* W2    = (const float*)d_in[3];
    const float* b2    = (const float*)d_in[4];
    const float* svec  = (const float*)d_in[5];
    const int*   src   = (const int*)d_in[6];
    const int*   dst   = (const int*)d_in[7];
    float* out = (float*)d_out;

    const int N = in_sizes[0] / INDIM;
    const int E = in_sizes[6];

    void *pv;
    cudaGetSymbolAddress(&pv, g_Hh);     uint32_t* H      = (uint32_t*)pv;
    cudaGetSymbolAddress(&pv, g_norm);   float*    nrm    = (float*)pv;
    cudaGetSymbolAddress(&pv, g_nrm2);   float*    nrm2   = (float*)pv;
    cudaGetSymbolAddress(&pv, g_sdeg);   float*    sdeg   = (float*)pv;
    cudaGetSymbolAddress(&pv, g_deg);    int*      deg    = (int*)pv;
    cudaGetSymbolAddress(&pv, g_rowptr); int*      rowptr = (int*)pv;
    cudaGetSymbolAddress(&pv, g_cursor); int*      cursor = (int*)pv;
    cudaGetSymbolAddress(&pv, g_bsum);   int*      bsum   = (int*)pv;
    cudaGetSymbolAddress(&pv, g_col);    int*      col    = (int*)pv;
    cudaGetSymbolAddress(&pv, g_w1h);    uint32_t* w1h    = (uint32_t*)pv;
    cudaGetSymbolAddress(&pv, g_w2h);    uint32_t* w2h    = (uint32_t*)pv;
    cudaGetSymbolAddress(&pv, g_w2l);    uint32_t* w2l    = (uint32_t*)pv;

    const size_t plane = (size_t)N * HLDH;
    const int nb = (N + 511) / 512;

    const int smem_p1 = (2 * TBM1 * ASU + 2 * 16 * BSTF) * 4;
    const int smem_p2 = (TBM1 * X1ST * 2 + 2 * 16 * W2ST * 2) * 4;
    const int smemF = smem_p1 > smem_p2 ? smem_p1 : smem_p2;
    cudaFuncSetAttribute(mlp_fused, cudaFuncAttributeMaxDynamicSharedMemorySize, smemF);

    // 0) pre-split weights
    decomp_hi<<<((INDIM / 2) * HIDD + 255) / 256, 256>>>(W1, w1h, INDIM, HIDD, HIDD);
    decomp_pair<<<((HIDD / 2) * 64 + 255) / 256, 256>>>(W2, w2h, w2l, HIDD, CDIM, 64);

    // 1) CSR build first (mlp epilogue needs nrm)
    cudaMemsetAsync(deg, 0, (size_t)N * sizeof(int));
    hist_kernel<<<(E + 255) / 256, 256>>>(dst, deg, E);
    norm_kernel<<<(N + 255) / 256, 256>>>(deg, nrm, nrm2, sdeg, N);
    scan_block<<<nb, 512>>>(deg, rowptr, bsum, N);
    scan_sums<<<1, 1024>>>(bsum, nb);
    scan_finish<<<(N + 255) / 256, 256>>>(rowptr, bsum, cursor, N, E);
    fill_kernel<<<(E + 255) / 256, 256>>>(src, dst, cursor, col, E);

    // 2) fused MLP -> t0 (packed fp16, pre-scaled by nrm)
    {
        dim3 grid((N + TBM1 - 1) / TBM1);
        mlp_fused<<<grid, 256, smemF>>>(feats, w1h, b1, w2h, w2l, b2, nrm, H, N, INDIM);
    }

    // 3) K propagation hops on packed fp16 planes
    for (int k = 1; k <= KHOP; k++) {
        const uint32_t* hin = H + (size_t)(k - 1) * plane;
        uint32_t* hout      = H + (size_t)k * plane;
        spmm_pull<<<(N * 32 + 255) / 256, 256>>>(rowptr, col, nrm2, hin, hout, N);
    }

    // 4) sigmoid-gated combine
    final_kernel<<<(N * 32 + 255) / 256, 256>>>(H, svec, sdeg, out, N);
}

// round 14
// speedup vs baseline: 1.0025x; 1.0025x over previous
#include <cuda_runtime.h>
#include <cuda_fp16.h>
#include <cstdint>

#define NMAX   100000
#define EMAX   1600000
#define CDIM   50
#define HLDH   32            // packed H row stride (uint32 = fp16x2), 128 B rows
#define HIDD   256
#define INDIM  500
#define KHOP   10

// ---------------- static scratch (no allocations allowed) ----------------
// 256-B alignment is load-bearing: each 128-B row must sit in ONE L2 line.
static __device__ __align__(256) uint32_t g_Hh[(size_t)(KHOP + 1) * NMAX * HLDH];
static __device__ float    g_norm[NMAX];    // deg^-1/2
static __device__ float    g_nrm2[NMAX];    // deg^-1
static __device__ float    g_sdeg[NMAX];    // deg^+1/2
static __device__ int      g_deg   [NMAX];
static __device__ int      g_rowptr[NMAX + 1];
static __device__ int      g_cursor[NMAX];
static __device__ int      g_bsum  [1024];
static __device__ int      g_col   [EMAX];
static __device__ __align__(16) uint32_t g_w1h[(INDIM / 2) * HIDD];  // W1 k-pair hi plane
static __device__ __align__(16) uint32_t g_w2h[(HIDD / 2) * 64];     // W2 padded ldp=64
static __device__ __align__(16) uint32_t g_w2l[(HIDD / 2) * 64];

// ================= fp16 helpers =================
__device__ __forceinline__ void split2(float x, float y, uint32_t& h2u, uint32_t& l2u) {
    __half2 h = __floats2half2_rn(x, y);
    float2 hf = __half22float2(h);
    __half2 l = __floats2half2_rn(x - hf.x, y - hf.y);
    h2u = *reinterpret_cast<uint32_t*>(&h);
    l2u = *reinterpret_cast<uint32_t*>(&l);
}

__device__ __forceinline__ uint32_t pack_h2(float x, float y) {
    __half2 h = __floats2half2_rn(x, y);
    return *reinterpret_cast<uint32_t*>(&h);
}

__device__ __forceinline__ float2 unpack_h2(uint32_t u) {
    __half2 h = *reinterpret_cast<__half2*>(&u);
    return __half22float2(h);
}

__device__ __forceinline__ void mma_f16(float* c, const uint32_t* a, const uint32_t* b) {
    asm volatile(
        "mma.sync.aligned.m16n8k16.row.col.f32.f16.f16.f32 "
        "{%0,%1,%2,%3}, {%4,%5,%6,%7}, {%8,%9}, {%0,%1,%2,%3};"
        : "+f"(c[0]), "+f"(c[1]), "+f"(c[2]), "+f"(c[3])
        : "r"(a[0]), "r"(a[1]), "r"(a[2]), "r"(a[3]), "r"(b[0]), "r"(b[1]));
}

__device__ __forceinline__ void cp_async16(uint32_t dst, const void* src, int sz) {
    asm volatile("cp.async.ca.shared.global [%0], [%1], 16, %2;"
                 :: "r"(dst), "l"(src), "r"(sz));
}
#define CP_COMMIT() asm volatile("cp.async.commit_group;")
#define CP_WAIT1()  asm volatile("cp.async.wait_group 1;")
#define CP_WAIT0()  asm volatile("cp.async.wait_group 0;")

// W [K][N] fp32 -> packed k-pair fp16 hi plane [K/2][ldp]
__global__ void decomp_hi(const float* __restrict__ W,
                          uint32_t* __restrict__ Wh2, int K, int N, int ldp) {
    int i = blockIdx.x * blockDim.x + threadIdx.x;
    if (i >= (K / 2) * ldp) return;
    int k2 = i / ldp, c = i % ldp;
    float x = (c < N) ? W[(size_t)(2 * k2) * N + c] : 0.f;
    float y = (c < N) ? W[(size_t)(2 * k2 + 1) * N + c] : 0.f;
    Wh2[i] = pack_h2(x, y);
}

// W [K][N] fp32 -> packed hi+lo planes (W2)
__global__ void decomp_pair(const float* __restrict__ W,
                            uint32_t* __restrict__ Wh2, uint32_t* __restrict__ Wl2,
                            int K, int N, int ldp) {
    int i = blockIdx.x * blockDim.x + threadIdx.x;
    if (i >= (K / 2) * ldp) return;
    int k2 = i / ldp, c = i % ldp;
    float x = (c < N) ? W[(size_t)(2 * k2) * N + c] : 0.f;
    float y = (c < N) ? W[(size_t)(2 * k2 + 1) * N + c] : 0.f;
    uint32_t h, l; split2(x, y, h, l);
    Wh2[i] = h; Wl2[i] = l;
}

// ================= fused MLP: t0(fp16) = nrm * (relu(feats@W1+b1) @ W2 + b2) =================
#define TBM1 64
#define TBK  32
#define ASU  20
#define BSTF 264
#define X1ST 132
#define W2ST 72

__global__ __launch_bounds__(256, 2)
void mlp_fused(const float* __restrict__ A,
               const uint32_t* __restrict__ Bh2g,
               const float* __restrict__ bias1,
               const uint32_t* __restrict__ W2hg, const uint32_t* __restrict__ W2lg,
               const float* __restrict__ bias2,
               const float* __restrict__ nrm,
               uint32_t* __restrict__ C, int M, int K) {
    extern __shared__ uint8_t dyn[];
    uint32_t* Ah = (uint32_t*)dyn;                 // [2][64][ASU]
    uint32_t* Bh = Ah + 2 * TBM1 * ASU;            // [2][16][BSTF]
    uint32_t* X1h = (uint32_t*)dyn;                // [64][X1ST]
    uint32_t* X1l = X1h + TBM1 * X1ST;
    uint32_t* W2h = X1l + TBM1 * X1ST;             // [2][16][W2ST]
    uint32_t* W2l = W2h + 2 * 16 * W2ST;

    const uint32_t sBh  = (uint32_t)__cvta_generic_to_shared(Bh);
    const uint32_t sW2h = (uint32_t)__cvta_generic_to_shared(W2h);
    const uint32_t sW2l = (uint32_t)__cvta_generic_to_shared(W2l);

    const int tid  = threadIdx.x;
    const int lane = tid & 31;
    const int wid  = tid >> 5;
    const int g    = lane >> 2;
    const int tg   = lane & 3;
    const int row0 = blockIdx.x * TBM1;
    const int K2   = K / 2;

    const int wm = (wid & 1) * 32;
    const int wn = (wid >> 1) * 64;

    float acc[2][8][4];
#pragma unroll
    for (int i = 0; i < 2; i++)
#pragma unroll
        for (int j = 0; j < 8; j++)
#pragma unroll
            for (int q = 0; q < 4; q++) acc[i][j][q] = 0.f;

    float4 areg[2];
    auto ldgA = [&](int kt) {
#pragma unroll
        for (int q = 0; q < 2; q++) {
            int chunk = tid + q * 256;
            int r = chunk >> 3, c4 = (chunk & 7) * 4;
            int gr = row0 + r, gk = kt + c4;
            float4 v = make_float4(0.f, 0.f, 0.f, 0.f);
            if (gr < M) {
                if (gk + 3 < K) {
                    v = *reinterpret_cast<const float4*>(A + (size_t)gr * K + gk);
                } else if (gk < K) {
                    const float* p = A + (size_t)gr * K;
                    v.x = p[gk];
                    v.y = (gk + 1 < K) ? p[gk + 1] : 0.f;
                    v.z = (gk + 2 < K) ? p[gk + 2] : 0.f;
                    v.w = (gk + 3 < K) ? p[gk + 3] : 0.f;
                }
            }
            areg[q] = v;
        }
    };
    auto stsA = [&](int buf) {
#pragma unroll
        for (int q = 0; q < 2; q++) {
            int chunk = tid + q * 256;
            int r = chunk >> 3, c4 = (chunk & 7) * 4;
            uint32_t h01 = pack_h2(areg[q].x, areg[q].y);
            uint32_t h23 = pack_h2(areg[q].z, areg[q].w);
            int base = (buf * TBM1 + r) * ASU + (c4 >> 1);
            *reinterpret_cast<uint2*>(&Ah[base]) = make_uint2(h01, h23);
        }
    };
    auto cpB = [&](int buf, int kt) {
        int k2t = kt >> 1;
#pragma unroll
        for (int q = 0; q < 4; q++) {
            int chunk = tid + q * 256;
            int r = chunk >> 6, c4 = (chunk & 63) * 4;
            int gk2 = k2t + r;
            int sz = (gk2 < K2) ? 16 : 0;
            const uint32_t* src = Bh2g + (size_t)(gk2 < K2 ? gk2 : 0) * HIDD + c4;
            uint32_t dst = sBh + (uint32_t)(((buf * 16 + r) * BSTF + c4) * 4);
            cp_async16(dst, src, sz);
        }
    };

    const int ktiles = (K + TBK - 1) / TBK;
    ldgA(0); stsA(0);
    cpB(0, 0); CP_COMMIT();

    int buf = 0;
    for (int t = 0; t < ktiles; t++) {
        if (t + 1 < ktiles) {
            ldgA((t + 1) * TBK);
            cpB(buf ^ 1, (t + 1) * TBK);
            CP_COMMIT();
            CP_WAIT1();
        } else {
            CP_WAIT0();
        }
        __syncthreads();

        const uint32_t* ab_h = Ah + buf * TBM1 * ASU;
        const uint32_t* bb_h = Bh + buf * 16 * BSTF;
#pragma unroll
        for (int ks = 0; ks < 2; ks++) {
            const int k2 = ks * 8;
            uint32_t ah[2][4];
#pragma unroll
            for (int mi = 0; mi < 2; mi++) {
                int m = wm + mi * 16;
                ah[mi][0] = ab_h[(m + g    ) * ASU + k2 + tg    ];
                ah[mi][1] = ab_h[(m + g + 8) * ASU + k2 + tg    ];
                ah[mi][2] = ab_h[(m + g    ) * ASU + k2 + 4 + tg];
                ah[mi][3] = ab_h[(m + g + 8) * ASU + k2 + 4 + tg];
            }
#pragma unroll
            for (int ni = 0; ni < 8; ni++) {
                int n = wn + ni * 8;
                uint32_t bh[2];
                bh[0] = bb_h[(k2 + tg    ) * BSTF + n + g];
                bh[1] = bb_h[(k2 + 4 + tg) * BSTF + n + g];
#pragma unroll
                for (int mi = 0; mi < 2; mi++)
                    mma_f16(acc[mi][ni], ah[mi], bh);
            }
        }
        if (t + 1 < ktiles) stsA(buf ^ 1);
        __syncthreads();
        buf ^= 1;
    }

    // ---------------- transition ----------------
    auto loadW2 = [&](int b, int k2t) {
#pragma unroll
        for (int q = 0; q < 2; q++) {
            int chunk = tid + q * 256;
            int plane = chunk >> 8;
            int cc = chunk & 255;
            int r = cc >> 4, c4 = (cc & 15) * 4;
            const uint32_t* src = (plane ? W2lg : W2hg) + (size_t)(k2t + r) * 64 + c4;
            uint32_t dst = (plane ? sW2l : sW2h) + (uint32_t)(((b * 16 + r) * W2ST + c4) * 4);
            cp_async16(dst, src, 16);
        }
    };

    loadW2(0, 0);
    CP_COMMIT();
#pragma unroll
    for (int mi = 0; mi < 2; mi++) {
#pragma unroll
        for (int ni = 0; ni < 8; ni++) {
            int c = wn + ni * 8 + 2 * tg;
            float bv0 = bias1[c], bv1 = bias1[c + 1];
            int rA = wm + mi * 16 + g;
            int rB = rA + 8;
            float v0 = fmaxf(acc[mi][ni][0] + bv0, 0.f);
            float v1 = fmaxf(acc[mi][ni][1] + bv1, 0.f);
            float v2 = fmaxf(acc[mi][ni][2] + bv0, 0.f);
            float v3 = fmaxf(acc[mi][ni][3] + bv1, 0.f);
            uint32_t h, l;
            split2(v0, v1, h, l);
            X1h[rA * X1ST + (c >> 1)] = h;
            X1l[rA * X1ST + (c >> 1)] = l;
            split2(v2, v3, h, l);
            X1h[rB * X1ST + (c >> 1)] = h;
            X1l[rB * X1ST + (c >> 1)] = l;
        }
    }

    // ---------------- phase 2 ----------------
    const int wm2 = (wid & 1) * 32;
    const int wn2 = (wid >> 1) * 16;

    float acc2[2][2][4];
#pragma unroll
    for (int i = 0; i < 2; i++)
#pragma unroll
        for (int j = 0; j < 2; j++)
#pragma unroll
            for (int q = 0; q < 4; q++) acc2[i][j][q] = 0.f;

    int buf2 = 0;
    for (int t = 0; t < 8; t++) {
        if (t + 1 < 8) {
            loadW2(buf2 ^ 1, (t + 1) * 16);
            CP_COMMIT();
            CP_WAIT1();
        } else {
            CP_WAIT0();
        }
        __syncthreads();

        const uint32_t* wb_h = W2h + buf2 * 16 * W2ST;
        const uint32_t* wb_l = W2l + buf2 * 16 * W2ST;
        const int k2base = t * 16;
#pragma unroll
        for (int ks = 0; ks < 2; ks++) {
            const int k2 = ks * 8;
            const int kc = k2base + k2;
            uint32_t ah[2][4], al[2][4], bh[2][2], bl[2][2];
#pragma unroll
            for (int mi = 0; mi < 2; mi++) {
                int m = wm2 + mi * 16;
                ah[mi][0] = X1h[(m + g    ) * X1ST + kc + tg    ];
                ah[mi][1] = X1h[(m + g + 8) * X1ST + kc + tg    ];
                ah[mi][2] = X1h[(m + g    ) * X1ST + kc + 4 + tg];
                ah[mi][3] = X1h[(m + g + 8) * X1ST + kc + 4 + tg];
                al[mi][0] = X1l[(m + g    ) * X1ST + kc + tg    ];
                al[mi][1] = X1l[(m + g + 8) * X1ST + kc + tg    ];
                al[mi][2] = X1l[(m + g    ) * X1ST + kc + 4 + tg];
                al[mi][3] = X1l[(m + g + 8) * X1ST + kc + 4 + tg];
            }
#pragma unroll
            for (int ni = 0; ni < 2; ni++) {
                int n = wn2 + ni * 8;
                bh[ni][0] = wb_h[(k2 + tg    ) * W2ST + n + g];
                bh[ni][1] = wb_h[(k2 + 4 + tg) * W2ST + n + g];
                bl[ni][0] = wb_l[(k2 + tg    ) * W2ST + n + g];
                bl[ni][1] = wb_l[(k2 + 4 + tg) * W2ST + n + g];
            }
#pragma unroll
            for (int mi = 0; mi < 2; mi++)
#pragma unroll
                for (int ni = 0; ni < 2; ni++) {
                    mma_f16(acc2[mi][ni], ah[mi], bh[ni]);
                    mma_f16(acc2[mi][ni], al[mi], bh[ni]);
                    mma_f16(acc2[mi][ni], ah[mi], bl[ni]);
                }
        }
        __syncthreads();
        buf2 ^= 1;
    }

    // epilogue 2: bias2, scale by nrm, write packed fp16 t0 row (stride HLDH)
#pragma unroll
    for (int mi = 0; mi < 2; mi++) {
#pragma unroll
        for (int ni = 0; ni < 2; ni++) {
            int c = wn2 + ni * 8 + 2 * tg;
            if (c >= CDIM) continue;
            float bv0 = bias2[c];
            float bv1 = (c + 1 < CDIM) ? bias2[c + 1] : 0.f;
            int r0 = row0 + wm2 + mi * 16 + g;
            int r1 = r0 + 8;
            if (r0 < M) {
                float nd = nrm[r0];
                float v0 = (acc2[mi][ni][0] + bv0) * nd;
                float v1 = (acc2[mi][ni][1] + bv1) * nd;
                C[(size_t)r0 * HLDH + (c >> 1)] = pack_h2(v0, v1);
            }
            if (r1 < M) {
                float nd = nrm[r1];
                float v2 = (acc2[mi][ni][2] + bv0) * nd;
                float v3 = (acc2[mi][ni][3] + bv1) * nd;
                C[(size_t)r1 * HLDH + (c >> 1)] = pack_h2(v2, v3);
            }
        }
    }
}

// ---------------- CSR build helpers ----------------
__global__ void hist_kernel(const int* __restrict__ dst, int* __restrict__ deg, int E) {
    int i = blockIdx.x * blockDim.x + threadIdx.x;
    if (i < E) atomicAdd(&deg[dst[i]], 1);
}

// scan + per-node norm factors fused (reads deg once)
__global__ void scan_block(const int* __restrict__ deg, int* __restrict__ rowptr,
                           int* __restrict__ bsum,
                           float* __restrict__ nrm, float* __restrict__ nrm2,
                           float* __restrict__ sdeg, int n) {
    __shared__ int sh[512];
    int tid = threadIdx.x;
    int gid = blockIdx.x * 512 + tid;
    int v = (gid < n) ? deg[gid] : 0;
    if (gid < n) {
        float d = (float)v;
        nrm[gid]  = rsqrtf(d);
        nrm2[gid] = 1.0f / d;
        sdeg[gid] = sqrtf(d);
    }
    sh[tid] = v;
    __syncthreads();
    for (int off = 1; off < 512; off <<= 1) {
        int t = (tid >= off) ? sh[tid - off] : 0;
        __syncthreads();
        sh[tid] += t;
        __syncthreads();
    }
    if (gid < n) rowptr[gid] = sh[tid] - v;
    if (tid == 511) bsum[blockIdx.x] = sh[511];
}

__global__ void scan_sums(int* __restrict__ bsum, int nb) {
    __shared__ int sh[1024];
    int tid = threadIdx.x;
    int v = (tid < nb) ? bsum[tid] : 0;
    sh[tid] = v;
    __syncthreads();
    for (int off = 1; off < 1024; off <<= 1) {
        int t = (tid >= off) ? sh[tid - off] : 0;
        __syncthreads();
        sh[tid] += t;
        __syncthreads();
    }
    if (tid < nb) bsum[tid] = sh[tid] - v;
}

__global__ void scan_finish(int* __restrict__ rowptr, const int* __restrict__ bsum,
                            int* __restrict__ cursor, int n, int E) {
    int gid = blockIdx.x * blockDim.x + threadIdx.x;
    if (gid < n) {
        int r = rowptr[gid] + bsum[gid / 512];
        rowptr[gid] = r;
        cursor[gid] = r;
    }
    if (gid == 0) rowptr[n] = E;
}

__global__ void fill_kernel(const int* __restrict__ src, const int* __restrict__ dst,
                            int* __restrict__ cursor, int* __restrict__ col, int E) {
    int e = blockIdx.x * blockDim.x + threadIdx.x;
    if (e >= E) return;
    int pos = atomicAdd(&cursor[dst[e]], 1);
    col[pos] = src[e];
}

// ---------------- pull-gather hop on packed fp16 planes ----------------
__global__ void spmm_pull(const int* __restrict__ rowptr, const int* __restrict__ col,
                          const float* __restrict__ nrm2,
                          const uint32_t* __restrict__ hin, uint32_t* __restrict__ hout,
                          int N) {
    int t = blockIdx.x * blockDim.x + threadIdx.x;
    int n = t >> 5;
    int lane = t & 31;
    if (n >= N) return;

    int beg = rowptr[n];
    int end = rowptr[n + 1];
    const bool act = (lane < CDIM / 2);

    float ax = 0.f, ay = 0.f;
    int j = beg;
    for (; j + 3 < end; j += 4) {
        int s0 = col[j], s1 = col[j + 1], s2 = col[j + 2], s3 = col[j + 3];
        if (act) {
            float2 v0 = unpack_h2(hin[(size_t)s0 * HLDH + lane]);
            float2 v1 = unpack_h2(hin[(size_t)s1 * HLDH + lane]);
            float2 v2 = unpack_h2(hin[(size_t)s2 * HLDH + lane]);
            float2 v3 = unpack_h2(hin[(size_t)s3 * HLDH + lane]);
            ax += (v0.x + v1.x) + (v2.x + v3.x);
            ay += (v0.y + v1.y) + (v2.y + v3.y);
        }
    }
    for (; j < end; j++) {
        int s0 = col[j];
        if (act) {
            float2 v0 = unpack_h2(hin[(size_t)s0 * HLDH + lane]);
            ax += v0.x;
            ay += v0.y;
        }
    }
    if (act) {
        float w = nrm2[n];
        hout[(size_t)n * HLDH + lane] = pack_h2(w * ax, w * ay);
    }
}

// ---------------- final sigmoid-gated combine (unscale by sqrt(deg)) ----------------
__global__ void final_kernel(const uint32_t* __restrict__ H, const float* __restrict__ s,
                             const float* __restrict__ sdeg,
                             float* __restrict__ out, int N) {
    int t = blockIdx.x * blockDim.x + threadIdx.x;
    int n = t >> 5;
    int lane = t & 31;
    if (n >= N) return;

    const bool act = (lane < CDIM / 2);
    const int  c2  = lane * 2;
    float sx = act ? s[c2] : 0.f;
    float sy = act ? s[c2 + 1] : 0.f;
    float inv = sdeg[n];

    float ax = 0.f, ay = 0.f;
    size_t plane = (size_t)N * HLDH;
    const uint32_t* base = H + (size_t)n * HLDH;

#pragma unroll
    for (int k = 0; k <= KHOP; k++) {
        float2 tv = act ? unpack_h2(base[(size_t)k * plane + lane]) : make_float2(0.f, 0.f);
        float hx = tv.x * inv, hy = tv.y * inv;
        float dot = hx * sx + hy * sy;
#pragma unroll
        for (int off = 16; off; off >>= 1)
            dot += __shfl_xor_sync(0xffffffffu, dot, off);
        float S = 1.f / (1.f + __expf(-dot));
        ax += S * hx;
        ay += S * hy;
    }
    if (act)
        *reinterpret_cast<float2*>(out + (size_t)n * CDIM + c2) = make_float2(ax, ay);
}

// ---------------- launch ----------------
extern "C" void kernel_launch(void* const* d_in, const int* in_sizes, int n_in,
                              void* d_out, int out_size) {
    const float* feats = (const float*)d_in[0];
    const float* W1    = (const float*)d_in[1];
    const float* b1    = (const float*)d_in[2];
    const float* W2    = (const float*)d_in[3];
    const float* b2    = (const float*)d_in[4];
    const float* svec  = (const float*)d_in[5];
    const int*   src   = (const int*)d_in[6];
    const int*   dst   = (const int*)d_in[7];
    float* out = (float*)d_out;

    const int N = in_sizes[0] / INDIM;
    const int E = in_sizes[6];

    void *pv;
    cudaGetSymbolAddress(&pv, g_Hh);     uint32_t* H      = (uint32_t*)pv;
    cudaGetSymbolAddress(&pv, g_norm);   float*    nrm    = (float*)pv;
    cudaGetSymbolAddress(&pv, g_nrm2);   float*    nrm2   = (float*)pv;
    cudaGetSymbolAddress(&pv, g_sdeg);   float*    sdeg   = (float*)pv;
    cudaGetSymbolAddress(&pv, g_deg);    int*      deg    = (int*)pv;
    cudaGetSymbolAddress(&pv, g_rowptr); int*      rowptr = (int*)pv;
    cudaGetSymbolAddress(&pv, g_cursor); int*      cursor = (int*)pv;
    cudaGetSymbolAddress(&pv, g_bsum);   int*      bsum   = (int*)pv;
    cudaGetSymbolAddress(&pv, g_col);    int*      col    = (int*)pv;
    cudaGetSymbolAddress(&pv, g_w1h);    uint32_t* w1h    = (uint32_t*)pv;
    cudaGetSymbolAddress(&pv, g_w2h);    uint32_t* w2h    = (uint32_t*)pv;
    cudaGetSymbolAddress(&pv, g_w2l);    uint32_t* w2l    = (uint32_t*)pv;

    const size_t plane = (size_t)N * HLDH;
    const int nb = (N + 511) / 512;

    const int smem_p1 = (2 * TBM1 * ASU + 2 * 16 * BSTF) * 4;
    const int smem_p2 = (TBM1 * X1ST * 2 + 2 * 16 * W2ST * 2) * 4;
    const int smemF = smem_p1 > smem_p2 ? smem_p1 : smem_p2;
    cudaFuncSetAttribute(mlp_fused, cudaFuncAttributeMaxDynamicSharedMemorySize, smemF);

    // 0) pre-split weights
    decomp_hi<<<((INDIM / 2) * HIDD + 255) / 256, 256>>>(W1, w1h, INDIM, HIDD, HIDD);
    decomp_pair<<<((HIDD / 2) * 64 + 255) / 256, 256>>>(W2, w2h, w2l, HIDD, CDIM, 64);

    // 1) CSR build (norm factors fused into scan_block)
    cudaMemsetAsync(deg, 0, (size_t)N * sizeof(int));
    hist_kernel<<<(E + 255) / 256, 256>>>(dst, deg, E);
    scan_block<<<nb, 512>>>(deg, rowptr, bsum, nrm, nrm2, sdeg, N);
    scan_sums<<<1, 1024>>>(bsum, nb);
    scan_finish<<<(N + 255) / 256, 256>>>(rowptr, bsum, cursor, N, E);
    fill_kernel<<<(E + 255) / 256, 256>>>(src, dst, cursor, col, E);

    // 2) fused MLP -> t0 (packed fp16, pre-scaled by nrm)
    {
        dim3 grid((N + TBM1 - 1) / TBM1);
        mlp_fused<<<grid, 256, smemF>>>(feats, w1h, b1, w2h, w2l, b2, nrm, H, N, INDIM);
    }

    // 3) K propagation hops on packed fp16 planes (rows line-aligned now)
    for (int k = 1; k <= KHOP; k++) {
        const uint32_t* hin = H + (size_t)(k - 1) * plane;
        uint32_t* hout      = H + (size_t)k * plane;
        spmm_pull<<<(N * 32 + 255) / 256, 256>>>(rowptr, col, nrm2, hin, hout, N);
    }

    // 4) sigmoid-gated combine
    final_kernel<<<(N * 32 + 255) / 256, 256>>>(H, svec, sdeg, out, N);
}

// round 15
// speedup vs baseline: 1.0138x; 1.0113x over previous
#include <cuda_runtime.h>
#include <cuda_fp16.h>
#include <cstdint>

#define NMAX   100000
#define EMAX   1600000
#define CDIM   50
#define HLD    64            // padded H row stride (floats)
#define HIDD   256
#define INDIM  500
#define KHOP   10

// ---------------- static scratch (no allocations allowed) ----------------
static __device__ __align__(256) float g_H [(size_t)(KHOP + 1) * NMAX * HLD];
static __device__ float    g_norm[NMAX];    // deg^-1/2
static __device__ float    g_nrm2[NMAX];    // deg^-1
static __device__ float    g_sdeg[NMAX];    // deg^+1/2
static __device__ int      g_deg   [NMAX];
static __device__ int      g_rowptr[NMAX + 1];
static __device__ int      g_cursor[NMAX];
static __device__ int      g_bsum  [1024];
static __device__ int      g_col   [EMAX];
static __device__ __align__(16) uint32_t g_w1h[(INDIM / 2) * HIDD];  // W1 k-pair hi plane
static __device__ __align__(16) uint32_t g_w2h[(HIDD / 2) * 64];     // W2 padded ldp=64
static __device__ __align__(16) uint32_t g_w2l[(HIDD / 2) * 64];

// ================= fp16 split helpers =================
__device__ __forceinline__ void split2(float x, float y, uint32_t& h2u, uint32_t& l2u) {
    __half2 h = __floats2half2_rn(x, y);
    float2 hf = __half22float2(h);
    __half2 l = __floats2half2_rn(x - hf.x, y - hf.y);
    h2u = *reinterpret_cast<uint32_t*>(&h);
    l2u = *reinterpret_cast<uint32_t*>(&l);
}

__device__ __forceinline__ uint32_t pack_h2(float x, float y) {
    __half2 h = __floats2half2_rn(x, y);
    return *reinterpret_cast<uint32_t*>(&h);
}

__device__ __forceinline__ void mma_f16(float* c, const uint32_t* a, const uint32_t* b) {
    asm volatile(
        "mma.sync.aligned.m16n8k16.row.col.f32.f16.f16.f32 "
        "{%0,%1,%2,%3}, {%4,%5,%6,%7}, {%8,%9}, {%0,%1,%2,%3};"
        : "+f"(c[0]), "+f"(c[1]), "+f"(c[2]), "+f"(c[3])
        : "r"(a[0]), "r"(a[1]), "r"(a[2]), "r"(a[3]), "r"(b[0]), "r"(b[1]));
}

__device__ __forceinline__ void cp_async16(uint32_t dst, const void* src, int sz) {
    asm volatile("cp.async.ca.shared.global [%0], [%1], 16, %2;"
                 :: "r"(dst), "l"(src), "r"(sz));
}
#define CP_COMMIT() asm volatile("cp.async.commit_group;")
#define CP_WAIT1()  asm volatile("cp.async.wait_group 1;")
#define CP_WAIT0()  asm volatile("cp.async.wait_group 0;")

// W [K][N] fp32 -> packed k-pair fp16 hi plane [K/2][ldp]
__global__ void decomp_hi(const float* __restrict__ W,
                          uint32_t* __restrict__ Wh2, int K, int N, int ldp) {
    int i = blockIdx.x * blockDim.x + threadIdx.x;
    if (i >= (K / 2) * ldp) return;
    int k2 = i / ldp, c = i % ldp;
    float x = (c < N) ? W[(size_t)(2 * k2) * N + c] : 0.f;
    float y = (c < N) ? W[(size_t)(2 * k2 + 1) * N + c] : 0.f;
    Wh2[i] = pack_h2(x, y);
}

// W [K][N] fp32 -> packed hi+lo planes (W2)
__global__ void decomp_pair(const float* __restrict__ W,
                            uint32_t* __restrict__ Wh2, uint32_t* __restrict__ Wl2,
                            int K, int N, int ldp) {
    int i = blockIdx.x * blockDim.x + threadIdx.x;
    if (i >= (K / 2) * ldp) return;
    int k2 = i / ldp, c = i % ldp;
    float x = (c < N) ? W[(size_t)(2 * k2) * N + c] : 0.f;
    float y = (c < N) ? W[(size_t)(2 * k2 + 1) * N + c] : 0.f;
    uint32_t h, l; split2(x, y, h, l);
    Wh2[i] = h; Wl2[i] = l;
}

// ================= fused MLP: t0 = nrm * (relu(feats@W1+b1) @ W2 + b2) =================
// Phase 1: single-term fp16. Phase 2: 3-term via smem x1.
#define TBM1 64
#define TBK  32
#define ASU  20
#define BSTF 264
#define X1ST 132
#define W2ST 72

__global__ __launch_bounds__(256, 2)
void mlp_fused(const float* __restrict__ A,
               const uint32_t* __restrict__ Bh2g,
               const float* __restrict__ bias1,
               const uint32_t* __restrict__ W2hg, const uint32_t* __restrict__ W2lg,
               const float* __restrict__ bias2,
               const float* __restrict__ nrm,
               float* __restrict__ C, int M, int K) {
    extern __shared__ uint8_t dyn[];
    uint32_t* Ah = (uint32_t*)dyn;                 // [2][64][ASU]
    uint32_t* Bh = Ah + 2 * TBM1 * ASU;            // [2][16][BSTF]
    uint32_t* X1h = (uint32_t*)dyn;                // [64][X1ST]
    uint32_t* X1l = X1h + TBM1 * X1ST;
    uint32_t* W2h = X1l + TBM1 * X1ST;             // [2][16][W2ST]
    uint32_t* W2l = W2h + 2 * 16 * W2ST;

    const uint32_t sBh  = (uint32_t)__cvta_generic_to_shared(Bh);
    const uint32_t sW2h = (uint32_t)__cvta_generic_to_shared(W2h);
    const uint32_t sW2l = (uint32_t)__cvta_generic_to_shared(W2l);

    const int tid  = threadIdx.x;
    const int lane = tid & 31;
    const int wid  = tid >> 5;
    const int g    = lane >> 2;
    const int tg   = lane & 3;
    const int row0 = blockIdx.x * TBM1;
    const int K2   = K / 2;

    const int wm = (wid & 1) * 32;
    const int wn = (wid >> 1) * 64;

    float acc[2][8][4];
#pragma unroll
    for (int i = 0; i < 2; i++)
#pragma unroll
        for (int j = 0; j < 8; j++)
#pragma unroll
            for (int q = 0; q < 4; q++) acc[i][j][q] = 0.f;

    float4 areg[2];
    auto ldgA = [&](int kt) {
#pragma unroll
        for (int q = 0; q < 2; q++) {
            int chunk = tid + q * 256;
            int r = chunk >> 3, c4 = (chunk & 7) * 4;
            int gr = row0 + r, gk = kt + c4;
            float4 v = make_float4(0.f, 0.f, 0.f, 0.f);
            if (gr < M) {
                if (gk + 3 < K) {
                    v = *reinterpret_cast<const float4*>(A + (size_t)gr * K + gk);
                } else if (gk < K) {
                    const float* p = A + (size_t)gr * K;
                    v.x = p[gk];
                    v.y = (gk + 1 < K) ? p[gk + 1] : 0.f;
                    v.z = (gk + 2 < K) ? p[gk + 2] : 0.f;
                    v.w = (gk + 3 < K) ? p[gk + 3] : 0.f;
                }
            }
            areg[q] = v;
        }
    };
    auto stsA = [&](int buf) {
#pragma unroll
        for (int q = 0; q < 2; q++) {
            int chunk = tid + q * 256;
            int r = chunk >> 3, c4 = (chunk & 7) * 4;
            uint32_t h01 = pack_h2(areg[q].x, areg[q].y);
            uint32_t h23 = pack_h2(areg[q].z, areg[q].w);
            int base = (buf * TBM1 + r) * ASU + (c4 >> 1);
            *reinterpret_cast<uint2*>(&Ah[base]) = make_uint2(h01, h23);
        }
    };
    auto cpB = [&](int buf, int kt) {
        int k2t = kt >> 1;
#pragma unroll
        for (int q = 0; q < 4; q++) {
            int chunk = tid + q * 256;
            int r = chunk >> 6, c4 = (chunk & 63) * 4;
            int gk2 = k2t + r;
            int sz = (gk2 < K2) ? 16 : 0;
            const uint32_t* src = Bh2g + (size_t)(gk2 < K2 ? gk2 : 0) * HIDD + c4;
            uint32_t dst = sBh + (uint32_t)(((buf * 16 + r) * BSTF + c4) * 4);
            cp_async16(dst, src, sz);
        }
    };

    const int ktiles = (K + TBK - 1) / TBK;
    ldgA(0); stsA(0);
    cpB(0, 0); CP_COMMIT();

    int buf = 0;
    for (int t = 0; t < ktiles; t++) {
        if (t + 1 < ktiles) {
            ldgA((t + 1) * TBK);
            cpB(buf ^ 1, (t + 1) * TBK);
            CP_COMMIT();
            CP_WAIT1();
        } else {
            CP_WAIT0();
        }
        __syncthreads();

        const uint32_t* ab_h = Ah + buf * TBM1 * ASU;
        const uint32_t* bb_h = Bh + buf * 16 * BSTF;
#pragma unroll
        for (int ks = 0; ks < 2; ks++) {
            const int k2 = ks * 8;
            uint32_t ah[2][4];
#pragma unroll
            for (int mi = 0; mi < 2; mi++) {
                int m = wm + mi * 16;
                ah[mi][0] = ab_h[(m + g    ) * ASU + k2 + tg    ];
                ah[mi][1] = ab_h[(m + g + 8) * ASU + k2 + tg    ];
                ah[mi][2] = ab_h[(m + g    ) * ASU + k2 + 4 + tg];
                ah[mi][3] = ab_h[(m + g + 8) * ASU + k2 + 4 + tg];
            }
#pragma unroll
            for (int ni = 0; ni < 8; ni++) {
                int n = wn + ni * 8;
                uint32_t bh[2];
                bh[0] = bb_h[(k2 + tg    ) * BSTF + n + g];
                bh[1] = bb_h[(k2 + 4 + tg) * BSTF + n + g];
#pragma unroll
                for (int mi = 0; mi < 2; mi++)
                    mma_f16(acc[mi][ni], ah[mi], bh);
            }
        }
        if (t + 1 < ktiles) stsA(buf ^ 1);
        __syncthreads();
        buf ^= 1;
    }

    // ---------------- transition ----------------
    auto loadW2 = [&](int b, int k2t) {
#pragma unroll
        for (int q = 0; q < 2; q++) {
            int chunk = tid + q * 256;
            int plane = chunk >> 8;
            int cc = chunk & 255;
            int r = cc >> 4, c4 = (cc & 15) * 4;
            const uint32_t* src = (plane ? W2lg : W2hg) + (size_t)(k2t + r) * 64 + c4;
            uint32_t dst = (plane ? sW2l : sW2h) + (uint32_t)(((b * 16 + r) * W2ST + c4) * 4);
            cp_async16(dst, src, 16);
        }
    };

    loadW2(0, 0);
    CP_COMMIT();
#pragma unroll
    for (int mi = 0; mi < 2; mi++) {
#pragma unroll
        for (int ni = 0; ni < 8; ni++) {
            int c = wn + ni * 8 + 2 * tg;
            float bv0 = bias1[c], bv1 = bias1[c + 1];
            int rA = wm + mi * 16 + g;
            int rB = rA + 8;
            float v0 = fmaxf(acc[mi][ni][0] + bv0, 0.f);
            float v1 = fmaxf(acc[mi][ni][1] + bv1, 0.f);
            float v2 = fmaxf(acc[mi][ni][2] + bv0, 0.f);
            float v3 = fmaxf(acc[mi][ni][3] + bv1, 0.f);
            uint32_t h, l;
            split2(v0, v1, h, l);
            X1h[rA * X1ST + (c >> 1)] = h;
            X1l[rA * X1ST + (c >> 1)] = l;
            split2(v2, v3, h, l);
            X1h[rB * X1ST + (c >> 1)] = h;
            X1l[rB * X1ST + (c >> 1)] = l;
        }
    }

    // ---------------- phase 2 ----------------
    const int wm2 = (wid & 1) * 32;
    const int wn2 = (wid >> 1) * 16;

    float acc2[2][2][4];
#pragma unroll
    for (int i = 0; i < 2; i++)
#pragma unroll
        for (int j = 0; j < 2; j++)
#pragma unroll
            for (int q = 0; q < 4; q++) acc2[i][j][q] = 0.f;

    int buf2 = 0;
    for (int t = 0; t < 8; t++) {
        if (t + 1 < 8) {
            loadW2(buf2 ^ 1, (t + 1) * 16);
            CP_COMMIT();
            CP_WAIT1();
        } else {
            CP_WAIT0();
        }
        __syncthreads();

        const uint32_t* wb_h = W2h + buf2 * 16 * W2ST;
        const uint32_t* wb_l = W2l + buf2 * 16 * W2ST;
        const int k2base = t * 16;
#pragma unroll
        for (int ks = 0; ks < 2; ks++) {
            const int k2 = ks * 8;
            const int kc = k2base + k2;
            uint32_t ah[2][4], al[2][4], bh[2][2], bl[2][2];
#pragma unroll
            for (int mi = 0; mi < 2; mi++) {
                int m = wm2 + mi * 16;
                ah[mi][0] = X1h[(m + g    ) * X1ST + kc + tg    ];
                ah[mi][1] = X1h[(m + g + 8) * X1ST + kc + tg    ];
                ah[mi][2] = X1h[(m + g    ) * X1ST + kc + 4 + tg];
                ah[mi][3] = X1h[(m + g + 8) * X1ST + kc + 4 + tg];
                al[mi][0] = X1l[(m + g    ) * X1ST + kc + tg    ];
                al[mi][1] = X1l[(m + g + 8) * X1ST + kc + tg    ];
                al[mi][2] = X1l[(m + g    ) * X1ST + kc + 4 + tg];
                al[mi][3] = X1l[(m + g + 8) * X1ST + kc + 4 + tg];
            }
#pragma unroll
            for (int ni = 0; ni < 2; ni++) {
                int n = wn2 + ni * 8;
                bh[ni][0] = wb_h[(k2 + tg    ) * W2ST + n + g];
                bh[ni][1] = wb_h[(k2 + 4 + tg) * W2ST + n + g];
                bl[ni][0] = wb_l[(k2 + tg    ) * W2ST + n + g];
                bl[ni][1] = wb_l[(k2 + 4 + tg) * W2ST + n + g];
            }
#pragma unroll
            for (int mi = 0; mi < 2; mi++)
#pragma unroll
                for (int ni = 0; ni < 2; ni++) {
                    mma_f16(acc2[mi][ni], ah[mi], bh[ni]);
                    mma_f16(acc2[mi][ni], al[mi], bh[ni]);
                    mma_f16(acc2[mi][ni], ah[mi], bl[ni]);
                }
        }
        __syncthreads();
        buf2 ^= 1;
    }

    // epilogue 2: bias2, scale by nrm, write fp32 t0 (stride HLD)
#pragma unroll
    for (int mi = 0; mi < 2; mi++) {
#pragma unroll
        for (int ni = 0; ni < 2; ni++) {
            int c = wn2 + ni * 8 + 2 * tg;
            if (c >= CDIM) continue;
            float bv0 = bias2[c];
            float bv1 = (c + 1 < CDIM) ? bias2[c + 1] : 0.f;
            int r0 = row0 + wm2 + mi * 16 + g;
            int r1 = r0 + 8;
            if (r0 < M) {
                float nd = nrm[r0];
                float v0 = (acc2[mi][ni][0] + bv0) * nd;
                float v1 = (acc2[mi][ni][1] + bv1) * nd;
                if (c + 1 < CDIM)
                    *reinterpret_cast<float2*>(C + (size_t)r0 * HLD + c) = make_float2(v0, v1);
                else
                    C[(size_t)r0 * HLD + c] = v0;
            }
            if (r1 < M) {
                float nd = nrm[r1];
                float v2 = (acc2[mi][ni][2] + bv0) * nd;
                float v3 = (acc2[mi][ni][3] + bv1) * nd;
                if (c + 1 < CDIM)
                    *reinterpret_cast<float2*>(C + (size_t)r1 * HLD + c) = make_float2(v2, v3);
                else
                    C[(size_t)r1 * HLD + c] = v2;
            }
        }
    }
}

// ---------------- CSR build helpers ----------------
__global__ void hist_kernel(const int* __restrict__ dst, int* __restrict__ deg, int E) {
    int i = blockIdx.x * blockDim.x + threadIdx.x;
    if (i < E) atomicAdd(&deg[dst[i]], 1);
}

// scan + per-node norm factors fused
__global__ void scan_block(const int* __restrict__ deg, int* __restrict__ rowptr,
                           int* __restrict__ bsum,
                           float* __restrict__ nrm, float* __restrict__ nrm2,
                           float* __restrict__ sdeg, int n) {
    __shared__ int sh[512];
    int tid = threadIdx.x;
    int gid = blockIdx.x * 512 + tid;
    int v = (gid < n) ? deg[gid] : 0;
    if (gid < n) {
        float d = (float)v;
        nrm[gid]  = rsqrtf(d);
        nrm2[gid] = 1.0f / d;
        sdeg[gid] = sqrtf(d);
    }
    sh[tid] = v;
    __syncthreads();
    for (int off = 1; off < 512; off <<= 1) {
        int t = (tid >= off) ? sh[tid - off] : 0;
        __syncthreads();
        sh[tid] += t;
        __syncthreads();
    }
    if (gid < n) rowptr[gid] = sh[tid] - v;
    if (tid == 511) bsum[blockIdx.x] = sh[511];
}

__global__ void scan_sums(int* __restrict__ bsum, int nb) {
    __shared__ int sh[1024];
    int tid = threadIdx.x;
    int v = (tid < nb) ? bsum[tid] : 0;
    sh[tid] = v;
    __syncthreads();
    for (int off = 1; off < 1024; off <<= 1) {
        int t = (tid >= off) ? sh[tid - off] : 0;
        __syncthreads();
        sh[tid] += t;
        __syncthreads();
    }
    if (tid < nb) bsum[tid] = sh[tid] - v;
}

__global__ void scan_finish(int* __restrict__ rowptr, const int* __restrict__ bsum,
                            int* __restrict__ cursor, int n, int E) {
    int gid = blockIdx.x * blockDim.x + threadIdx.x;
    if (gid < n) {
        int r = rowptr[gid] + bsum[gid / 512];
        rowptr[gid] = r;
        cursor[gid] = r;
    }
    if (gid == 0) rowptr[n] = E;
}

__global__ void fill_kernel(const int* __restrict__ src, const int* __restrict__ dst,
                            int* __restrict__ cursor, int* __restrict__ col, int E) {
    int e = blockIdx.x * blockDim.x + threadIdx.x;
    if (e >= E) return;
    int pos = atomicAdd(&cursor[dst[e]], 1);
    col[pos] = src[e];
}

// ---------------- pull-gather hop: warp-staged indices, deep MLP ----------------
// t_out[d] = nrm2[d] * sum_{s in N(d)} t_in[s]
__global__ void spmm_pull(const int* __restrict__ rowptr, const int* __restrict__ col,
                          const float* __restrict__ nrm2,
                          const float* __restrict__ hin, float* __restrict__ hout,
                          int N) {
    int t = blockIdx.x * blockDim.x + threadIdx.x;
    int n = t >> 5;
    int lane = t & 31;
    if (n >= N) return;

    int beg = rowptr[n];
    int end = rowptr[n + 1];
    const bool act = (lane < CDIM / 2);
    const int  c2  = lane * 2;

    float ax = 0.f, ay = 0.f;
    for (int base = beg; base < end; base += 32) {
        // one coalesced load stages up to 32 neighbor indices in the warp
        int myidx = (base + lane < end) ? col[base + lane] : 0;
        int cnt = end - base;
        if (cnt > 32) cnt = 32;

        int q = 0;
        for (; q + 3 < cnt; q += 4) {
            int s0 = __shfl_sync(0xffffffffu, myidx, q);
            int s1 = __shfl_sync(0xffffffffu, myidx, q + 1);
            int s2 = __shfl_sync(0xffffffffu, myidx, q + 2);
            int s3 = __shfl_sync(0xffffffffu, myidx, q + 3);
            if (act) {
                float2 v0 = *reinterpret_cast<const float2*>(hin + (size_t)s0 * HLD + c2);
                float2 v1 = *reinterpret_cast<const float2*>(hin + (size_t)s1 * HLD + c2);
                float2 v2 = *reinterpret_cast<const float2*>(hin + (size_t)s2 * HLD + c2);
                float2 v3 = *reinterpret_cast<const float2*>(hin + (size_t)s3 * HLD + c2);
                ax += (v0.x + v1.x) + (v2.x + v3.x);
                ay += (v0.y + v1.y) + (v2.y + v3.y);
            }
        }
        for (; q < cnt; q++) {
            int s0 = __shfl_sync(0xffffffffu, myidx, q);
            if (act) {
                float2 v0 = *reinterpret_cast<const float2*>(hin + (size_t)s0 * HLD + c2);
                ax += v0.x;
                ay += v0.y;
            }
        }
    }
    if (act) {
        float w = nrm2[n];
        *reinterpret_cast<float2*>(hout + (size_t)n * HLD + c2) = make_float2(w * ax, w * ay);
    }
}

// ---------------- final sigmoid-gated combine (unscale by sqrt(deg)) ----------------
__global__ void final_kernel(const float* __restrict__ H, const float* __restrict__ s,
                             const float* __restrict__ sdeg,
                             float* __restrict__ out, int N) {
    int t = blockIdx.x * blockDim.x + threadIdx.x;
    int n = t >> 5;
    int lane = t & 31;
    if (n >= N) return;

    const bool act = (lane < CDIM / 2);
    const int  c2  = lane * 2;
    float sx = act ? s[c2] : 0.f;
    float sy = act ? s[c2 + 1] : 0.f;
    float inv = sdeg[n];

    float ax = 0.f, ay = 0.f;
    size_t plane = (size_t)N * HLD;
    const float* base = H + (size_t)n * HLD;

#pragma unroll
    for (int k = 0; k <= KHOP; k++) {
        float2 tv = act ? *reinterpret_cast<const float2*>(base + (size_t)k * plane + c2)
                        : make_float2(0.f, 0.f);
        float hx = tv.x * inv, hy = tv.y * inv;
        float dot = hx * sx + hy * sy;
#pragma unroll
        for (int off = 16; off; off >>= 1)
            dot += __shfl_xor_sync(0xffffffffu, dot, off);
        float S = 1.f / (1.f + __expf(-dot));
        ax += S * hx;
        ay += S * hy;
    }
    if (act)
        *reinterpret_cast<float2*>(out + (size_t)n * CDIM + c2) = make_float2(ax, ay);
}

// ---------------- launch ----------------
extern "C" void kernel_launch(void* const* d_in, const int* in_sizes, int n_in,
                              void* d_out, int out_size) {
    const float* feats = (const float*)d_in[0];
    const float* W1    = (const float*)d_in[1];
    const float* b1    = (const float*)d_in[2];
    const float* W2    = (const float*)d_in[3];
    const float* b2    = (const float*)d_in[4];
    const float* svec  = (const float*)d_in[5];
    const int*   src   = (const int*)d_in[6];
    const int*   dst   = (const int*)d_in[7];
    float* out = (float*)d_out;

    const int N = in_sizes[0] / INDIM;
    const int E = in_sizes[6];

    void *pv;
    cudaGetSymbolAddress(&pv, g_H);      float*    H      = (float*)pv;
    cudaGetSymbolAddress(&pv, g_norm);   float*    nrm    = (float*)pv;
    cudaGetSymbolAddress(&pv, g_nrm2);   float*    nrm2   = (float*)pv;
    cudaGetSymbolAddress(&pv, g_sdeg);   float*    sdeg   = (float*)pv;
    cudaGetSymbolAddress(&pv, g_deg);    int*      deg    = (int*)pv;
    cudaGetSymbolAddress(&pv, g_rowptr); int*      rowptr = (int*)pv;
    cudaGetSymbolAddress(&pv, g_cursor); int*      cursor = (int*)pv;
    cudaGetSymbolAddress(&pv, g_bsum);   int*      bsum   = (int*)pv;
    cudaGetSymbolAddress(&pv, g_col);    int*      col    = (int*)pv;
    cudaGetSymbolAddress(&pv, g_w1h);    uint32_t* w1h    = (uint32_t*)pv;
    cudaGetSymbolAddress(&pv, g_w2h);    uint32_t* w2h    = (uint32_t*)pv;
    cudaGetSymbolAddress(&pv, g_w2l);    uint32_t* w2l    = (uint32_t*)pv;

    const size_t plane = (size_t)N * HLD;
    const int nb = (N + 511) / 512;

    const int smem_p1 = (2 * TBM1 * ASU + 2 * 16 * BSTF) * 4;
    const int smem_p2 = (TBM1 * X1ST * 2 + 2 * 16 * W2ST * 2) * 4;
    const int smemF = smem_p1 > smem_p2 ? smem_p1 : smem_p2;
    cudaFuncSetAttribute(mlp_fused, cudaFuncAttributeMaxDynamicSharedMemorySize, smemF);

    // 0) pre-split weights
    decomp_hi<<<((INDIM / 2) * HIDD + 255) / 256, 256>>>(W1, w1h, INDIM, HIDD, HIDD);
    decomp_pair<<<((HIDD / 2) * 64 + 255) / 256, 256>>>(W2, w2h, w2l, HIDD, CDIM, 64);

    // 1) CSR build (norm factors fused into scan_block)
    cudaMemsetAsync(deg, 0, (size_t)N * sizeof(int));
    hist_kernel<<<(E + 255) / 256, 256>>>(dst, deg, E);
    scan_block<<<nb, 512>>>(deg, rowptr, bsum, nrm, nrm2, sdeg, N);
    scan_sums<<<1, 1024>>>(bsum, nb);
    scan_finish<<<(N + 255) / 256, 256>>>(rowptr, bsum, cursor, N, E);
    fill_kernel<<<(E + 255) / 256, 256>>>(src, dst, cursor, col, E);

    // 2) fused MLP -> t0 (fp32, pre-scaled by nrm)
    {
        dim3 grid((N + TBM1 - 1) / TBM1);
        mlp_fused<<<grid, 256, smemF>>>(feats, w1h, b1, w2h, w2l, b2, nrm, H, N, INDIM);
    }

    // 3) K propagation hops (warp-staged gather)
    for (int k = 1; k <= KHOP; k++) {
        const float* hin = H + (size_t)(k - 1) * plane;
        float* hout      = H + (size_t)k * plane;
        spmm_pull<<<(N * 32 + 255) / 256, 256>>>(rowptr, col, nrm2, hin, hout, N);
    }

    // 4) sigmoid-gated combine
    final_kernel<<<(N * 32 + 255) / 256, 256>>>(H, svec, sdeg, out, N);
}

// round 17
// speedup vs baseline: 1.0668x; 1.0523x over previous
#include <cuda_runtime.h>
#include <cuda_fp16.h>
#include <cstdint>

#define NMAX   100000
#define EMAX   1600000
#define CDIM   50
#define HLD    64            // padded H row stride (floats)
#define HIDD   256
#define INDIM  500
#define KHOP   10

// ---------------- static scratch (no allocations allowed) ----------------
static __device__ __align__(256) float g_H [(size_t)(KHOP + 1) * NMAX * HLD];
static __device__ float    g_norm[NMAX];    // deg^-1/2
static __device__ float    g_nrm2[NMAX];    // deg^-1
static __device__ float    g_sdeg[NMAX];    // deg^+1/2
static __device__ int      g_deg   [NMAX];
static __device__ int      g_rowptr[NMAX + 1];
static __device__ int      g_cursor[NMAX];
static __device__ int      g_bsum  [1024];
static __device__ int      g_col   [EMAX];
static __device__ __align__(16) uint32_t g_w1h[(INDIM / 2) * HIDD];
static __device__ __align__(16) uint32_t g_w2h[(HIDD / 2) * 64];
static __device__ __align__(16) uint32_t g_w2l[(HIDD / 2) * 64];

// ================= fp16 split helpers =================
__device__ __forceinline__ void split2(float x, float y, uint32_t& h2u, uint32_t& l2u) {
    __half2 h = __floats2half2_rn(x, y);
    float2 hf = __half22float2(h);
    __half2 l = __floats2half2_rn(x - hf.x, y - hf.y);
    h2u = *reinterpret_cast<uint32_t*>(&h);
    l2u = *reinterpret_cast<uint32_t*>(&l);
}

__device__ __forceinline__ uint32_t pack_h2(float x, float y) {
    __half2 h = __floats2half2_rn(x, y);
    return *reinterpret_cast<uint32_t*>(&h);
}

__device__ __forceinline__ void mma_f16(float* c, const uint32_t* a, const uint32_t* b) {
    asm volatile(
        "mma.sync.aligned.m16n8k16.row.col.f32.f16.f16.f32 "
        "{%0,%1,%2,%3}, {%4,%5,%6,%7}, {%8,%9}, {%0,%1,%2,%3};"
        : "+f"(c[0]), "+f"(c[1]), "+f"(c[2]), "+f"(c[3])
        : "r"(a[0]), "r"(a[1]), "r"(a[2]), "r"(a[3]), "r"(b[0]), "r"(b[1]));
}

__device__ __forceinline__ void cp_async16(uint32_t dst, const void* src, int sz) {
    asm volatile("cp.async.ca.shared.global [%0], [%1], 16, %2;"
                 :: "r"(dst), "l"(src), "r"(sz));
}
#define CP_COMMIT() asm volatile("cp.async.commit_group;")
#define CP_WAIT1()  asm volatile("cp.async.wait_group 1;")
#define CP_WAIT0()  asm volatile("cp.async.wait_group 0;")

__global__ void decomp_hi(const float* __restrict__ W,
                          uint32_t* __restrict__ Wh2, int K, int N, int ldp) {
    int i = blockIdx.x * blockDim.x + threadIdx.x;
    if (i >= (K / 2) * ldp) return;
    int k2 = i / ldp, c = i % ldp;
    float x = (c < N) ? W[(size_t)(2 * k2) * N + c] : 0.f;
    float y = (c < N) ? W[(size_t)(2 * k2 + 1) * N + c] : 0.f;
    Wh2[i] = pack_h2(x, y);
}

__global__ void decomp_pair(const float* __restrict__ W,
                            uint32_t* __restrict__ Wh2, uint32_t* __restrict__ Wl2,
                            int K, int N, int ldp) {
    int i = blockIdx.x * blockDim.x + threadIdx.x;
    if (i >= (K / 2) * ldp) return;
    int k2 = i / ldp, c = i % ldp;
    float x = (c < N) ? W[(size_t)(2 * k2) * N + c] : 0.f;
    float y = (c < N) ? W[(size_t)(2 * k2 + 1) * N + c] : 0.f;
    uint32_t h, l; split2(x, y, h, l);
    Wh2[i] = h; Wl2[i] = l;
}

// ================= fused MLP (round-12 proven config) =================
#define TBM1 64
#define TBK  32
#define ASU  20
#define BSTF 264
#define X1ST 132
#define W2ST 72

__global__ __launch_bounds__(256, 2)
void mlp_fused(const float* __restrict__ A,
               const uint32_t* __restrict__ Bh2g,
               const float* __restrict__ bias1,
               const uint32_t* __restrict__ W2hg, const uint32_t* __restrict__ W2lg,
               const float* __restrict__ bias2,
               const float* __restrict__ nrm,
               float* __restrict__ C, int M, int K) {
    extern __shared__ uint8_t dyn[];
    uint32_t* Ah = (uint32_t*)dyn;
    uint32_t* Bh = Ah + 2 * TBM1 * ASU;
    uint32_t* X1h = (uint32_t*)dyn;
    uint32_t* X1l = X1h + TBM1 * X1ST;
    uint32_t* W2h = X1l + TBM1 * X1ST;
    uint32_t* W2l = W2h + 2 * 16 * W2ST;

    const uint32_t sBh  = (uint32_t)__cvta_generic_to_shared(Bh);
    const uint32_t sW2h = (uint32_t)__cvta_generic_to_shared(W2h);
    const uint32_t sW2l = (uint32_t)__cvta_generic_to_shared(W2l);

    const int tid  = threadIdx.x;
    const int lane = tid & 31;
    const int wid  = tid >> 5;
    const int g    = lane >> 2;
    const int tg   = lane & 3;
    const int row0 = blockIdx.x * TBM1;
    const int K2   = K / 2;

    const int wm = (wid & 1) * 32;
    const int wn = (wid >> 1) * 64;

    float acc[2][8][4];
#pragma unroll
    for (int i = 0; i < 2; i++)
#pragma unroll
        for (int j = 0; j < 8; j++)
#pragma unroll
            for (int q = 0; q < 4; q++) acc[i][j][q] = 0.f;

    float4 areg[2];
    auto ldgA = [&](int kt) {
#pragma unroll
        for (int q = 0; q < 2; q++) {
            int chunk = tid + q * 256;
            int r = chunk >> 3, c4 = (chunk & 7) * 4;
            int gr = row0 + r, gk = kt + c4;
            float4 v = make_float4(0.f, 0.f, 0.f, 0.f);
            if (gr < M) {
                if (gk + 3 < K) {
                    v = *reinterpret_cast<const float4*>(A + (size_t)gr * K + gk);
                } else if (gk < K) {
                    const float* p = A + (size_t)gr * K;
                    v.x = p[gk];
                    v.y = (gk + 1 < K) ? p[gk + 1] : 0.f;
                    v.z = (gk + 2 < K) ? p[gk + 2] : 0.f;
                    v.w = (gk + 3 < K) ? p[gk + 3] : 0.f;
                }
            }
            areg[q] = v;
        }
    };
    auto stsA = [&](int buf) {
#pragma unroll
        for (int q = 0; q < 2; q++) {
            int chunk = tid + q * 256;
            int r = chunk >> 3, c4 = (chunk & 7) * 4;
            uint32_t h01 = pack_h2(areg[q].x, areg[q].y);
            uint32_t h23 = pack_h2(areg[q].z, areg[q].w);
            int base = (buf * TBM1 + r) * ASU + (c4 >> 1);
            *reinterpret_cast<uint2*>(&Ah[base]) = make_uint2(h01, h23);
        }
    };
    auto cpB = [&](int buf, int kt) {
        int k2t = kt >> 1;
#pragma unroll
        for (int q = 0; q < 4; q++) {
            int chunk = tid + q * 256;
            int r = chunk >> 6, c4 = (chunk & 63) * 4;
            int gk2 = k2t + r;
            int sz = (gk2 < K2) ? 16 : 0;
            const uint32_t* src = Bh2g + (size_t)(gk2 < K2 ? gk2 : 0) * HIDD + c4;
            uint32_t dst = sBh + (uint32_t)(((buf * 16 + r) * BSTF + c4) * 4);
            cp_async16(dst, src, sz);
        }
    };

    const int ktiles = (K + TBK - 1) / TBK;
    ldgA(0); stsA(0);
    cpB(0, 0); CP_COMMIT();

    int buf = 0;
    for (int t = 0; t < ktiles; t++) {
        if (t + 1 < ktiles) {
            ldgA((t + 1) * TBK);
            cpB(buf ^ 1, (t + 1) * TBK);
            CP_COMMIT();
            CP_WAIT1();
        } else {
            CP_WAIT0();
        }
        __syncthreads();

        const uint32_t* ab_h = Ah + buf * TBM1 * ASU;
        const uint32_t* bb_h = Bh + buf * 16 * BSTF;
#pragma unroll
        for (int ks = 0; ks < 2; ks++) {
            const int k2 = ks * 8;
            uint32_t ah[2][4];
#pragma unroll
            for (int mi = 0; mi < 2; mi++) {
                int m = wm + mi * 16;
                ah[mi][0] = ab_h[(m + g    ) * ASU + k2 + tg    ];
                ah[mi][1] = ab_h[(m + g + 8) * ASU + k2 + tg    ];
                ah[mi][2] = ab_h[(m + g    ) * ASU + k2 + 4 + tg];
                ah[mi][3] = ab_h[(m + g + 8) * ASU + k2 + 4 + tg];
            }
#pragma unroll
            for (int ni = 0; ni < 8; ni++) {
                int n = wn + ni * 8;
                uint32_t bh[2];
                bh[0] = bb_h[(k2 + tg    ) * BSTF + n + g];
                bh[1] = bb_h[(k2 + 4 + tg) * BSTF + n + g];
#pragma unroll
                for (int mi = 0; mi < 2; mi++)
                    mma_f16(acc[mi][ni], ah[mi], bh);
            }
        }
        if (t + 1 < ktiles) stsA(buf ^ 1);
        __syncthreads();
        buf ^= 1;
    }

    // ---------------- transition ----------------
    auto loadW2 = [&](int b, int k2t) {
#pragma unroll
        for (int q = 0; q < 2; q++) {
            int chunk = tid + q * 256;
            int plane = chunk >> 8;
            int cc = chunk & 255;
            int r = cc >> 4, c4 = (cc & 15) * 4;
            const uint32_t* src = (plane ? W2lg : W2hg) + (size_t)(k2t + r) * 64 + c4;
            uint32_t dst = (plane ? sW2l : sW2h) + (uint32_t)(((b * 16 + r) * W2ST + c4) * 4);
            cp_async16(dst, src, 16);
        }
    };

    loadW2(0, 0);
    CP_COMMIT();
#pragma unroll
    for (int mi = 0; mi < 2; mi++) {
#pragma unroll
        for (int ni = 0; ni < 8; ni++) {
            int c = wn + ni * 8 + 2 * tg;
            float bv0 = bias1[c], bv1 = bias1[c + 1];
            int rA = wm + mi * 16 + g;
            int rB = rA + 8;
            float v0 = fmaxf(acc[mi][ni][0] + bv0, 0.f);
            float v1 = fmaxf(acc[mi][ni][1] + bv1, 0.f);
            float v2 = fmaxf(acc[mi][ni][2] + bv0, 0.f);
            float v3 = fmaxf(acc[mi][ni][3] + bv1, 0.f);
            uint32_t h, l;
            split2(v0, v1, h, l);
            X1h[rA * X1ST + (c >> 1)] = h;
            X1l[rA * X1ST + (c >> 1)] = l;
            split2(v2, v3, h, l);
            X1h[rB * X1ST + (c >> 1)] = h;
            X1l[rB * X1ST + (c >> 1)] = l;
        }
    }

    // ---------------- phase 2 ----------------
    const int wm2 = (wid & 1) * 32;
    const int wn2 = (wid >> 1) * 16;

    float acc2[2][2][4];
#pragma unroll
    for (int i = 0; i < 2; i++)
#pragma unroll
        for (int j = 0; j < 2; j++)
#pragma unroll
            for (int q = 0; q < 4; q++) acc2[i][j][q] = 0.f;

    int buf2 = 0;
    for (int t = 0; t < 8; t++) {
        if (t + 1 < 8) {
            loadW2(buf2 ^ 1, (t + 1) * 16);
            CP_COMMIT();
            CP_WAIT1();
        } else {
            CP_WAIT0();
        }
        __syncthreads();

        const uint32_t* wb_h = W2h + buf2 * 16 * W2ST;
        const uint32_t* wb_l = W2l + buf2 * 16 * W2ST;
        const int k2base = t * 16;
#pragma unroll
        for (int ks = 0; ks < 2; ks++) {
            const int k2 = ks * 8;
            const int kc = k2base + k2;
            uint32_t ah[2][4], al[2][4], bh[2][2], bl[2][2];
#pragma unroll
            for (int mi = 0; mi < 2; mi++) {
                int m = wm2 + mi * 16;
                ah[mi][0] = X1h[(m + g    ) * X1ST + kc + tg    ];
                ah[mi][1] = X1h[(m + g + 8) * X1ST + kc + tg    ];
                ah[mi][2] = X1h[(m + g    ) * X1ST + kc + 4 + tg];
                ah[mi][3] = X1h[(m + g + 8) * X1ST + kc + 4 + tg];
                al[mi][0] = X1l[(m + g    ) * X1ST + kc + tg    ];
                al[mi][1] = X1l[(m + g + 8) * X1ST + kc + tg    ];
                al[mi][2] = X1l[(m + g    ) * X1ST + kc + 4 + tg];
                al[mi][3] = X1l[(m + g + 8) * X1ST + kc + 4 + tg];
            }
#pragma unroll
            for (int ni = 0; ni < 2; ni++) {
                int n = wn2 + ni * 8;
                bh[ni][0] = wb_h[(k2 + tg    ) * W2ST + n + g];
                bh[ni][1] = wb_h[(k2 + 4 + tg) * W2ST + n + g];
                bl[ni][0] = wb_l[(k2 + tg    ) * W2ST + n + g];
                bl[ni][1] = wb_l[(k2 + 4 + tg) * W2ST + n + g];
            }
#pragma unroll
            for (int mi = 0; mi < 2; mi++)
#pragma unroll
                for (int ni = 0; ni < 2; ni++) {
                    mma_f16(acc2[mi][ni], ah[mi], bh[ni]);
                    mma_f16(acc2[mi][ni], al[mi], bh[ni]);
                    mma_f16(acc2[mi][ni], ah[mi], bl[ni]);
                }
        }
        __syncthreads();
        buf2 ^= 1;
    }

#pragma unroll
    for (int mi = 0; mi < 2; mi++) {
#pragma unroll
        for (int ni = 0; ni < 2; ni++) {
            int c = wn2 + ni * 8 + 2 * tg;
            if (c >= CDIM) continue;
            float bv0 = bias2[c];
            float bv1 = (c + 1 < CDIM) ? bias2[c + 1] : 0.f;
            int r0 = row0 + wm2 + mi * 16 + g;
            int r1 = r0 + 8;
            if (r0 < M) {
                float nd = nrm[r0];
                float v0 = (acc2[mi][ni][0] + bv0) * nd;
                float v1 = (acc2[mi][ni][1] + bv1) * nd;
                if (c + 1 < CDIM)
                    *reinterpret_cast<float2*>(C + (size_t)r0 * HLD + c) = make_float2(v0, v1);
                else
                    C[(size_t)r0 * HLD + c] = v0;
            }
            if (r1 < M) {
                float nd = nrm[r1];
                float v2 = (acc2[mi][ni][2] + bv0) * nd;
                float v3 = (acc2[mi][ni][3] + bv1) * nd;
                if (c + 1 < CDIM)
                    *reinterpret_cast<float2*>(C + (size_t)r1 * HLD + c) = make_float2(v2, v3);
                else
                    C[(size_t)r1 * HLD + c] = v2;
            }
        }
    }
}

// ---------------- CSR build helpers ----------------
__global__ void hist_kernel(const int* __restrict__ dst, int* __restrict__ deg, int E) {
    int i = blockIdx.x * blockDim.x + threadIdx.x;
    if (i < E) atomicAdd(&deg[dst[i]], 1);
}

__global__ void scan_block(const int* __restrict__ deg, int* __restrict__ rowptr,
                           int* __restrict__ bsum,
                           float* __restrict__ nrm, float* __restrict__ nrm2,
                           float* __restrict__ sdeg, int n) {
    __shared__ int sh[512];
    int tid = threadIdx.x;
    int gid = blockIdx.x * 512 + tid;
    int v = (gid < n) ? deg[gid] : 0;
    if (gid < n) {
        float d = (float)v;
        nrm[gid]  = rsqrtf(d);
        nrm2[gid] = 1.0f / d;
        sdeg[gid] = sqrtf(d);
    }
    sh[tid] = v;
    __syncthreads();
    for (int off = 1; off < 512; off <<= 1) {
        int t = (tid >= off) ? sh[tid - off] : 0;
        __syncthreads();
        sh[tid] += t;
        __syncthreads();
    }
    if (gid < n) rowptr[gid] = sh[tid] - v;
    if (tid == 511) bsum[blockIdx.x] = sh[511];
}

__global__ void scan_sums(int* __restrict__ bsum, int nb) {
    __shared__ int sh[1024];
    int tid = threadIdx.x;
    int v = (tid < nb) ? bsum[tid] : 0;
    sh[tid] = v;
    __syncthreads();
    for (int off = 1; off < 1024; off <<= 1) {
        int t = (tid >= off) ? sh[tid - off] : 0;
        __syncthreads();
        sh[tid] += t;
        __syncthreads();
    }
    if (tid < nb) bsum[tid] = sh[tid] - v;
}

__global__ void scan_finish(int* __restrict__ rowptr, const int* __restrict__ bsum,
                            int* __restrict__ cursor, int n, int E) {
    int gid = blockIdx.x * blockDim.x + threadIdx.x;
    if (gid < n) {
        int r = rowptr[gid] + bsum[gid / 512];
        rowptr[gid] = r;
        cursor[gid] = r;
    }
    if (gid == 0) rowptr[n] = E;
}

__global__ void fill_kernel(const int* __restrict__ src, const int* __restrict__ dst,
                            int* __restrict__ cursor, int* __restrict__ col, int E) {
    int e = blockIdx.x * blockDim.x + threadIdx.x;
    if (e >= E) return;
    int pos = atomicAdd(&cursor[dst[e]], 1);
    col[pos] = src[e];
}

// ---------------- pull-gather hop (direct col loads, unroll-8) ----------------
__global__ void spmm_pull(const int* __restrict__ rowptr, const int* __restrict__ col,
                          const float* __restrict__ nrm2,
                          const float* __restrict__ hin, float* __restrict__ hout,
                          int N) {
    int t = blockIdx.x * blockDim.x + threadIdx.x;
    int n = t >> 5;
    int lane = t & 31;
    if (n >= N) return;

    int beg = rowptr[n];
    int end = rowptr[n + 1];
    const bool act = (lane < CDIM / 2);
    const int  c2  = lane * 2;

    float ax = 0.f, ay = 0.f;
    int j = beg;
    for (; j + 7 < end; j += 8) {
        int s0 = col[j],     s1 = col[j + 1], s2 = col[j + 2], s3 = col[j + 3];
        int s4 = col[j + 4], s5 = col[j + 5], s6 = col[j + 6], s7 = col[j + 7];
        if (act) {
            float2 v0 = *reinterpret_cast<const float2*>(hin + (size_t)s0 * HLD + c2);
            float2 v1 = *reinterpret_cast<const float2*>(hin + (size_t)s1 * HLD + c2);
            float2 v2 = *reinterpret_cast<const float2*>(hin + (size_t)s2 * HLD + c2);
            float2 v3 = *reinterpret_cast<const float2*>(hin + (size_t)s3 * HLD + c2);
            float2 v4 = *reinterpret_cast<const float2*>(hin + (size_t)s4 * HLD + c2);
            float2 v5 = *reinterpret_cast<const float2*>(hin + (size_t)s5 * HLD + c2);
            float2 v6 = *reinterpret_cast<const float2*>(hin + (size_t)s6 * HLD + c2);
            float2 v7 = *reinterpret_cast<const float2*>(hin + (size_t)s7 * HLD + c2);
            ax += ((v0.x + v1.x) + (v2.x + v3.x)) + ((v4.x + v5.x) + (v6.x + v7.x));
            ay += ((v0.y + v1.y) + (v2.y + v3.y)) + ((v4.y + v5.y) + (v6.y + v7.y));
        }
    }
    for (; j + 3 < end; j += 4) {
        int s0 = col[j], s1 = col[j + 1], s2 = col[j + 2], s3 = col[j + 3];
        if (act) {
            float2 v0 = *reinterpret_cast<const float2*>(hin + (size_t)s0 * HLD + c2);
            float2 v1 = *reinterpret_cast<const float2*>(hin + (size_t)s1 * HLD + c2);
            float2 v2 = *reinterpret_cast<const float2*>(hin + (size_t)s2 * HLD + c2);
            float2 v3 = *reinterpret_cast<const float2*>(hin + (size_t)s3 * HLD + c2);
            ax += (v0.x + v1.x) + (v2.x + v3.x);
            ay += (v0.y + v1.y) + (v2.y + v3.y);
        }
    }
    for (; j < end; j++) {
        int s0 = col[j];
        if (act) {
            float2 v0 = *reinterpret_cast<const float2*>(hin + (size_t)s0 * HLD + c2);
            ax += v0.x;
            ay += v0.y;
        }
    }
    if (act) {
        float w = nrm2[n];
        *reinterpret_cast<float2*>(hout + (size_t)n * HLD + c2) = make_float2(w * ax, w * ay);
    }
}

// ---------------- final hop fused with gating combine ----------------
// Computes t10 in registers from plane 9, then out[n] = sum_k S_k * h_k.
__global__ void spmm_final(const int* __restrict__ rowptr, const int* __restrict__ col,
                           const float* __restrict__ nrm2, const float* __restrict__ sdeg,
                           const float* __restrict__ H, const float* __restrict__ s,
                           float* __restrict__ out, int N) {
    int t = blockIdx.x * blockDim.x + threadIdx.x;
    int n = t >> 5;
    int lane = t & 31;
    if (n >= N) return;

    int beg = rowptr[n];
    int end = rowptr[n + 1];
    const bool act = (lane < CDIM / 2);
    const int  c2  = lane * 2;
    size_t plane = (size_t)N * HLD;
    const float* p9 = H + (size_t)(KHOP - 1) * plane;

    float ax = 0.f, ay = 0.f;
    int j = beg;
    for (; j + 7 < end; j += 8) {
        int s0 = col[j],     s1 = col[j + 1], s2 = col[j + 2], s3 = col[j + 3];
        int s4 = col[j + 4], s5 = col[j + 5], s6 = col[j + 6], s7 = col[j + 7];
        if (act) {
            float2 v0 = *reinterpret_cast<const float2*>(p9 + (size_t)s0 * HLD + c2);
            float2 v1 = *reinterpret_cast<const float2*>(p9 + (size_t)s1 * HLD + c2);
            float2 v2 = *reinterpret_cast<const float2*>(p9 + (size_t)s2 * HLD + c2);
            float2 v3 = *reinterpret_cast<const float2*>(p9 + (size_t)s3 * HLD + c2);
            float2 v4 = *reinterpret_cast<const float2*>(p9 + (size_t)s4 * HLD + c2);
            float2 v5 = *reinterpret_cast<const float2*>(p9 + (size_t)s5 * HLD + c2);
            float2 v6 = *reinterpret_cast<const float2*>(p9 + (size_t)s6 * HLD + c2);
            float2 v7 = *reinterpret_cast<const float2*>(p9 + (size_t)s7 * HLD + c2);
            ax += ((v0.x + v1.x) + (v2.x + v3.x)) + ((v4.x + v5.x) + (v6.x + v7.x));
            ay += ((v0.y + v1.y) + (v2.y + v3.y)) + ((v4.y + v5.y) + (v6.y + v7.y));
        }
    }
    for (; j + 3 < end; j += 4) {
        int s0 = col[j], s1 = col[j + 1], s2 = col[j + 2], s3 = col[j + 3];
        if (act) {
            float2 v0 = *reinterpret_cast<const float2*>(p9 + (size_t)s0 * HLD + c2);
            float2 v1 = *reinterpret_cast<const float2*>(p9 + (size_t)s1 * HLD + c2);
            float2 v2 = *reinterpret_cast<const float2*>(p9 + (size_t)s2 * HLD + c2);
            float2 v3 = *reinterpret_cast<const float2*>(p9 + (size_t)s3 * HLD + c2);
            ax += (v0.x + v1.x) + (v2.x + v3.x);
            ay += (v0.y + v1.y) + (v2.y + v3.y);
        }
    }
    for (; j < end; j++) {
        int s0 = col[j];
        if (act) {
            float2 v0 = *reinterpret_cast<const float2*>(p9 + (size_t)s0 * HLD + c2);
            ax += v0.x;
            ay += v0.y;
        }
    }
    // t10 (pre-scaled form)
    float w = nrm2[n];
    float t10x = w * ax, t10y = w * ay;

    // gating combine
    float sx = act ? s[c2] : 0.f;
    float sy = act ? s[c2 + 1] : 0.f;
    float inv = sdeg[n];

    float ox = 0.f, oy = 0.f;
    const float* base = H + (size_t)n * HLD;
#pragma unroll
    for (int k = 0; k <= KHOP; k++) {
        float hx, hy;
        if (k < KHOP) {
            float2 tv = act ? *reinterpret_cast<const float2*>(base + (size_t)k * plane + c2)
                            : make_float2(0.f, 0.f);
            hx = tv.x * inv; hy = tv.y * inv;
        } else {
            hx = act ? t10x * inv : 0.f;
            hy = act ? t10y * inv : 0.f;
        }
        float dot = hx * sx + hy * sy;
#pragma unroll
        for (int off = 16; off; off >>= 1)
            dot += __shfl_xor_sync(0xffffffffu, dot, off);
        float S = 1.f / (1.f + __expf(-dot));
        ox += S * hx;
        oy += S * hy;
    }
    if (act)
        *reinterpret_cast<float2*>(out + (size_t)n * CDIM + c2) = make_float2(ox, oy);
}

// ---------------- launch ----------------
extern "C" void kernel_launch(void* const* d_in, const int* in_sizes, int n_in,
                              void* d_out, int out_size) {
    const float* feats = (const float*)d_in[0];
    const float* W1    = (const float*)d_in[1];
    const float* b1    = (const float*)d_in[2];
    const float* W2    = (const float*)d_in[3];
    const float* b2    = (const float*)d_in[4];
    const float* svec  = (const float*)d_in[5];
    const int*   src   = (const int*)d_in[6];
    const int*   dst   = (const int*)d_in[7];
    float* out = (float*)d_out;

    const int N = in_sizes[0] / INDIM;
    const int E = in_sizes[6];

    void *pv;
    cudaGetSymbolAddress(&pv, g_H);      float*    H      = (float*)pv;
    cudaGetSymbolAddress(&pv, g_norm);   float*    nrm    = (float*)pv;
    cudaGetSymbolAddress(&pv, g_nrm2);   float*    nrm2   = (float*)pv;
    cudaGetSymbolAddress(&pv, g_sdeg);   float*    sdeg   = (float*)pv;
    cudaGetSymbolAddress(&pv, g_deg);    int*      deg    = (int*)pv;
    cudaGetSymbolAddress(&pv, g_rowptr); int*      rowptr = (int*)pv;
    cudaGetSymbolAddress(&pv, g_cursor); int*      cursor = (int*)pv;
    cudaGetSymbolAddress(&pv, g_bsum);   int*      bsum   = (int*)pv;
    cudaGetSymbolAddress(&pv, g_col);    int*      col    = (int*)pv;
    cudaGetSymbolAddress(&pv, g_w1h);    uint32_t* w1h    = (uint32_t*)pv;
    cudaGetSymbolAddress(&pv, g_w2h);    uint32_t* w2h    = (uint32_t*)pv;
    cudaGetSymbolAddress(&pv, g_w2l);    uint32_t* w2l    = (uint32_t*)pv;

    const size_t plane = (size_t)N * HLD;
    const int nb = (N + 511) / 512;

    const int smem_p1 = (2 * TBM1 * ASU + 2 * 16 * BSTF) * 4;
    const int smem_p2 = (TBM1 * X1ST * 2 + 2 * 16 * W2ST * 2) * 4;
    const int smemF = smem_p1 > smem_p2 ? smem_p1 : smem_p2;
    cudaFuncSetAttribute(mlp_fused, cudaFuncAttributeMaxDynamicSharedMemorySize, smemF);

    // 0) pre-split weights
    decomp_hi<<<((INDIM / 2) * HIDD + 255) / 256, 256>>>(W1, w1h, INDIM, HIDD, HIDD);
    decomp_pair<<<((HIDD / 2) * 64 + 255) / 256, 256>>>(W2, w2h, w2l, HIDD, CDIM, 64);

    // 1) CSR build
    cudaMemsetAsync(deg, 0, (size_t)N * sizeof(int));
    hist_kernel<<<(E + 255) / 256, 256>>>(dst, deg, E);
    scan_block<<<nb, 512>>>(deg, rowptr, bsum, nrm, nrm2, sdeg, N);
    scan_sums<<<1, 1024>>>(bsum, nb);
    scan_finish<<<(N + 255) / 256, 256>>>(rowptr, bsum, cursor, N, E);
    fill_kernel<<<(E + 255) / 256, 256>>>(src, dst, cursor, col, E);

    // 2) fused MLP -> t0
    {
        dim3 grid((N + TBM1 - 1) / TBM1);
        mlp_fused<<<grid, 256, smemF>>>(feats, w1h, b1, w2h, w2l, b2, nrm, H, N, INDIM);
    }

    // 3) hops 1..9
    for (int k = 1; k < KHOP; k++) {
        const float* hin = H + (size_t)(k - 1) * plane;
        float* hout      = H + (size_t)k * plane;
        spmm_pull<<<(N * 32 + 255) / 256, 256>>>(rowptr, col, nrm2, hin, hout, N);
    }

    // 4) hop 10 fused with gating combine
    spmm_final<<<(N * 32 + 255) / 256, 256>>>(rowptr, col, nrm2, sdeg, H, svec, out, N);
}